// round 1
// baseline (speedup 1.0000x reference)
#include <cuda_runtime.h>
#include <math.h>

#define NIN   12
#define NOUT  4
#define NHID  512
#define NU    40
#define NBLK  10          // NU / NOUT
#define NB    108         // B_hat rows = NIN*(N-1)
#define NINEQ 148
#define BATCH 4096
#define IPM_ITERS 20
#define SIGMA 0.1f
#define BIGF  1000000000.0f
#define EPSF  0.0001f
#define NT    128

// -------- device globals (no allocation allowed) --------
__device__ float g_Q[NU * NU];          // Q_hat
__device__ float g_B[NB * NU];          // B_hat
__device__ float g_h[NINEQ];            // h
__device__ float g_p[BATCH * NU];       // MLP output

__device__ __forceinline__ float lrelu(float x) { return x > 0.f ? x : 0.01f * x; }

// ================= setup: build Q_hat, B_hat, h =================
__global__ void setup_kernel(const float* __restrict__ L, const float* __restrict__ LP,
                             const float* __restrict__ LR, const float* __restrict__ A,
                             const float* __restrict__ Bm, const float* __restrict__ u0,
                             const float* __restrict__ s0) {
    __shared__ float sQx[144], sP[144], sR[16], sBp[9 * 48];
    __shared__ float sBh[NB * NU];
    __shared__ float sM[NB * NU];
    int tid = threadIdx.x;

    for (int idx = tid; idx < 144; idx += NT) {
        int i = idx / 12, j = idx % 12;
        int mn = i < j ? i : j;
        float a = 0.f, b = 0.f;
        for (int k = 0; k <= mn; k++) {
            a += L[i * 12 + k] * L[j * 12 + k];
            b += LP[i * 12 + k] * LP[j * 12 + k];
        }
        sQx[idx] = a + (i == j ? EPSF : 0.f);
        sP[idx]  = b + (i == j ? EPSF : 0.f);
    }
    for (int idx = tid; idx < 16; idx += NT) {
        int i = idx / 4, j = idx % 4;
        int mn = i < j ? i : j;
        float a = 0.f;
        for (int k = 0; k <= mn; k++) a += LR[i * 4 + k] * LR[j * 4 + k];
        sR[idx] = a + (i == j ? EPSF : 0.f);
    }
    if (tid < 48) sBp[tid] = Bm[tid];
    __syncthreads();

    // Bp[m] = A @ Bp[m-1], m = 1..8
    for (int m = 1; m < 9; m++) {
        if (tid < 48) {
            int i = tid / 4, o = tid % 4;
            float v = 0.f;
            for (int k = 0; k < 12; k++) v += A[i * 12 + k] * sBp[(m - 1) * 48 + k * 4 + o];
            sBp[m * 48 + tid] = v;   // disjoint from reads (block m vs m-1)
        }
        __syncthreads();
    }

    // B_hat block (rb, cb) = Bp[rb - cb] for cb <= rb
    for (int idx = tid; idx < NB * NU; idx += NT) {
        int row = idx / NU, col = idx % NU;
        int rb = row / 12, i = row % 12, cb = col / 4, o = col % 4;
        float v = (cb <= rb) ? sBp[(rb - cb) * 48 + i * 4 + o] : 0.f;
        sBh[idx] = v;
        g_B[idx] = v;
    }
    __syncthreads();

    // M = Q_diag @ B_hat  (block diagonal: 8x Qx then P)
    for (int idx = tid; idx < NB * NU; idx += NT) {
        int row = idx / NU, col = idx % NU;
        int rb = row / 12, i = row % 12;
        const float* Qd = (rb < 8) ? sQx : sP;
        float a = 0.f;
        for (int k = 0; k < 12; k++) a += Qd[i * 12 + k] * sBh[(rb * 12 + k) * NU + col];
        sM[idx] = a;
    }
    __syncthreads();

    // Q_hat = B_hat^T M + R_diag
    for (int idx = tid; idx < NU * NU; idx += NT) {
        int a_ = idx / NU, b_ = idx % NU;
        float v = (a_ / 4 == b_ / 4) ? sR[(a_ % 4) * 4 + (b_ % 4)] : 0.f;
        for (int r = 0; r < NB; r++) v += sBh[r * NU + a_] * sM[r * NU + b_];
        g_Q[idx] = v;
    }

    // h = G u0 + s0 ; G = [I ; B_hat]
    for (int j = tid; j < NINEQ; j += NT) {
        float v = s0[j];
        if (j < NU) v += u0[j];
        else {
            for (int i = 0; i < NU; i++) v += sBh[(j - NU) * NU + i] * u0[i];
        }
        g_h[j] = v;
    }
}

// ================= MLP: p = lrelu(lrelu(x W1^T + b1) W2^T + b2) =================
__global__ void mlp_kernel(const float* __restrict__ x, const float* __restrict__ W1,
                           const float* __restrict__ b1, const float* __restrict__ W2,
                           const float* __restrict__ b2) {
    __shared__ float hbuf[4][NHID];
    int warp = threadIdx.x >> 5, lane = threadIdx.x & 31;
    int row = blockIdx.x * 4 + warp;

    float xr[NIN];
#pragma unroll
    for (int c = 0; c < NIN; c++) xr[c] = x[row * NIN + c];

#pragma unroll
    for (int t = 0; t < NHID / 32; t++) {
        int j = lane + 32 * t;
        const float* w = W1 + j * NIN;
        float acc = b1[j];
#pragma unroll
        for (int c = 0; c < NIN; c++) acc += w[c] * xr[c];
        hbuf[warp][j] = lrelu(acc);
    }
    __syncwarp();

    for (int k = 0; k < NU; k++) {
        const float* w = W2 + k * NHID;
        float acc = 0.f;
#pragma unroll
        for (int t = 0; t < NHID / 32; t++) {
            int j = lane + 32 * t;
            acc += w[j] * hbuf[warp][j];
        }
#pragma unroll
        for (int o = 16; o; o >>= 1) acc += __shfl_xor_sync(0xffffffffu, acc, o);
        if (lane == 0) g_p[row * NU + k] = lrelu(acc + b2[k]);
    }
}

// ================= IPM solve, one CTA per batch item =================
__global__ void __launch_bounds__(NT) ipm_kernel(float* __restrict__ out) {
    __shared__ float sQ[NU * 41];
    __shared__ float sB[NB * 41];
    __shared__ float sH[NU * 41];
    __shared__ float sh_[NINEQ], sp_[NU], su[NU], ss[NINEQ], slam[NINEQ];
    __shared__ float srp[NINEQ], sv[NINEQ], sd[NINEQ], sds[NINEQ], sdl[NINEQ];
    __shared__ float srhs[NU], sdu[NU], sLd[NU];
    __shared__ float sred[4];
    __shared__ float smu, salpha;

    int tid = threadIdx.x;
    int b = blockIdx.x;

    for (int idx = tid; idx < NU * NU; idx += NT) sQ[(idx / NU) * 41 + idx % NU] = g_Q[idx];
    for (int idx = tid; idx < NB * NU; idx += NT) sB[(idx / NU) * 41 + idx % NU] = g_B[idx];
    for (int j = tid; j < NINEQ; j += NT) { sh_[j] = g_h[j]; ss[j] = 1.f; slam[j] = 1.f; }
    for (int i = tid; i < NU; i += NT) { sp_[i] = g_p[b * NU + i]; su[i] = 0.f; }
    __syncthreads();

    for (int it = 0; it < IPM_ITERS; it++) {
        // mu = mean(s * lam)
        float ls = 0.f;
        for (int j = tid; j < NINEQ; j += NT) ls += ss[j] * slam[j];
#pragma unroll
        for (int o = 16; o; o >>= 1) ls += __shfl_xor_sync(0xffffffffu, ls, o);
        if ((tid & 31) == 0) sred[tid >> 5] = ls;
        __syncthreads();
        if (tid == 0) smu = (sred[0] + sred[1] + sred[2] + sred[3]) * (1.0f / 148.0f);
        __syncthreads();
        float mu = smu;

        // d = lam/s ; rp = G u + s - h ; v = SIGMA*mu/s + d*rp
        for (int j = tid; j < NINEQ; j += NT) {
            float sj = ss[j], lj = slam[j];
            float dj = lj / sj;
            sd[j] = dj;
            float rpj;
            if (j < NU) rpj = su[j];
            else {
                const float* br = sB + (j - NU) * 41;
                float a = 0.f;
#pragma unroll
                for (int i = 0; i < NU; i++) a += br[i] * su[i];
                rpj = a;
            }
            rpj += sj - sh_[j];
            srp[j] = rpj;
            sv[j] = SIGMA * mu / sj + dj * rpj;
        }
        __syncthreads();

        // H = Q + diag(d[:40]) + B^T diag(d[40:]) B  (threads 0..99, 4x4 blocks)
        // rhs = -(uQ + p + v[:40] + B^T v[40:])      (threads 100..127)
        if (tid < 100) {
            int bi = tid / 10, bk = tid % 10;
            float acc[4][4];
#pragma unroll
            for (int a = 0; a < 4; a++)
#pragma unroll
                for (int c = 0; c < 4; c++) {
                    int i = 4 * bi + a, k = 4 * bk + c;
                    acc[a][c] = sQ[i * 41 + k] + (i == k ? sd[i] : 0.f);
                }
            for (int j = 0; j < NB; j++) {
                float dj = sd[NU + j];
                const float* br = sB + j * 41;
                float ga[4], gb[4];
#pragma unroll
                for (int a = 0; a < 4; a++) ga[a] = dj * br[4 * bi + a];
#pragma unroll
                for (int c = 0; c < 4; c++) gb[c] = br[4 * bk + c];
#pragma unroll
                for (int a = 0; a < 4; a++)
#pragma unroll
                    for (int c = 0; c < 4; c++) acc[a][c] += ga[a] * gb[c];
            }
#pragma unroll
            for (int a = 0; a < 4; a++)
#pragma unroll
                for (int c = 0; c < 4; c++) sH[(4 * bi + a) * 41 + 4 * bk + c] = acc[a][c];
        } else {
            for (int i = tid - 100; i < NU; i += 28) {
                float a = sp_[i] + sv[i];
                const float* qr = sQ + i * 41;
#pragma unroll
                for (int k = 0; k < NU; k++) a += qr[k] * su[k];
                for (int j = 0; j < NB; j++) a += sv[NU + j] * sB[j * 41 + i];
                srhs[i] = -a;
            }
        }
        __syncthreads();

        // Cholesky (lower), diag kept in sLd, scaled column in sH
        for (int k = 0; k < NU; k++) {
            float hkk = sH[k * 41 + k];
            float sq = sqrtf(hkk);
            float inv = 1.0f / sq;
            if (tid == 0) sLd[k] = sq;
            for (int i = k + 1 + tid; i < NU; i += NT) sH[i * 41 + k] *= inv;
            __syncthreads();
            int n = NU - 1 - k;
            for (int idx = tid; idx < n * n; idx += NT) {
                int i = k + 1 + idx / n, j = k + 1 + idx % n;
                sH[i * 41 + j] -= sH[i * 41 + k] * sH[j * 41 + k];
            }
            __syncthreads();
        }

        // Triangular solves by warp 0 (lane holds rows lane and 32+lane)
        if (tid < 32) {
            int lane = tid;
            float b0 = srhs[lane];
            float b1 = (lane < 8) ? srhs[32 + lane] : 0.f;
            // forward: L y = rhs
            for (int k = 0; k < NU; k++) {
                float src = (k < 32) ? b0 : b1;
                float yk = __shfl_sync(0xffffffffu, src, k & 31) / sLd[k];
                if (k < 32) { if (lane == k) b0 = yk; }
                else        { if (lane == k - 32) b1 = yk; }
                if (lane > k) b0 -= sH[lane * 41 + k] * yk;
                if (lane < 8 && 32 + lane > k) b1 -= sH[(32 + lane) * 41 + k] * yk;
            }
            // backward: L^T x = y
            for (int k = NU - 1; k >= 0; k--) {
                float src = (k < 32) ? b0 : b1;
                float xk = __shfl_sync(0xffffffffu, src, k & 31) / sLd[k];
                if (k < 32) { if (lane == k) b0 = xk; }
                else        { if (lane == k - 32) b1 = xk; }
                if (lane < k) b0 -= sH[k * 41 + lane] * xk;
                if (lane < 8 && 32 + lane < k) b1 -= sH[k * 41 + 32 + lane] * xk;
            }
            sdu[lane] = b0;
            if (lane < 8) sdu[32 + lane] = b1;
        }
        __syncthreads();

        // ds, dlam, step length
        float amin = BIGF;
        for (int j = tid; j < NINEQ; j += NT) {
            float gdu;
            if (j < NU) gdu = sdu[j];
            else {
                const float* br = sB + (j - NU) * 41;
                float a = 0.f;
#pragma unroll
                for (int i = 0; i < NU; i++) a += br[i] * sdu[i];
                gdu = a;
            }
            float dsj = -srp[j] - gdu;
            float dlj = sv[j] - slam[j] + sd[j] * gdu;
            sds[j] = dsj;
            sdl[j] = dlj;
            float a1 = (dsj < 0.f) ? -ss[j] / dsj : BIGF;
            float a2 = (dlj < 0.f) ? -slam[j] / dlj : BIGF;
            amin = fminf(amin, fminf(a1, a2));
        }
#pragma unroll
        for (int o = 16; o; o >>= 1) amin = fminf(amin, __shfl_xor_sync(0xffffffffu, amin, o));
        if ((tid & 31) == 0) sred[tid >> 5] = amin;
        __syncthreads();
        if (tid == 0) {
            float m = fminf(fminf(sred[0], sred[1]), fminf(sred[2], sred[3]));
            salpha = fminf(1.0f, 0.99f * m);
        }
        __syncthreads();
        float alpha = salpha;
        for (int j = tid; j < NINEQ; j += NT) {
            ss[j] += alpha * sds[j];
            slam[j] += alpha * sdl[j];
        }
        for (int i = tid; i < NU; i += NT) su[i] += alpha * sdu[i];
        __syncthreads();
    }

    // Q_value = 0.5 u'Qu + p'u ; u0 = u[0]
    float part = 0.f;
    for (int i = tid; i < NU; i += NT) {
        const float* qr = sQ + i * 41;
        float qu = 0.f;
#pragma unroll
        for (int k = 0; k < NU; k++) qu += qr[k] * su[k];
        part += su[i] * (0.5f * qu + sp_[i]);
    }
#pragma unroll
    for (int o = 16; o; o >>= 1) part += __shfl_xor_sync(0xffffffffu, part, o);
    if ((tid & 31) == 0) sred[tid >> 5] = part;
    __syncthreads();
    if (tid == 0) {
        out[b] = sred[0] + sred[1] + sred[2] + sred[3];
        out[BATCH + b] = su[0];
    }
}

// ================= launch =================
extern "C" void kernel_launch(void* const* d_in, const int* in_sizes, int n_in,
                              void* d_out, int out_size) {
    const float* x  = (const float*)d_in[0];
    const float* W1 = (const float*)d_in[1];
    const float* b1 = (const float*)d_in[2];
    const float* W2 = (const float*)d_in[3];
    const float* b2 = (const float*)d_in[4];
    const float* L  = (const float*)d_in[5];
    const float* LP = (const float*)d_in[6];
    const float* LR = (const float*)d_in[7];
    const float* A  = (const float*)d_in[8];
    const float* Bm = (const float*)d_in[9];
    const float* u0 = (const float*)d_in[10];
    const float* s0 = (const float*)d_in[11];

    setup_kernel<<<1, NT>>>(L, LP, LR, A, Bm, u0, s0);
    mlp_kernel<<<BATCH / 4, NT>>>(x, W1, b1, W2, b2);
    ipm_kernel<<<BATCH, NT>>>((float*)d_out);
}

// round 2
// speedup vs baseline: 1.6945x; 1.6945x over previous
#include <cuda_runtime.h>
#include <math.h>

#define NIN   12
#define NOUT  4
#define NHID  512
#define NU    40
#define NB    108         // B_hat rows = NIN*(N-1)
#define NINEQ 148
#define BATCH 4096
#define IPM_ITERS 20
#define SIGMA 0.1f
#define BIGF  1000000000.0f
#define EPSF  0.0001f
#define NT    128

// -------- device globals (no allocation allowed) --------
__device__ float g_Q[NU * NU];          // Q_hat
__device__ float g_B[NB * NU];          // B_hat
__device__ float g_h[NINEQ];            // h
__device__ float g_p[BATCH * NU];       // MLP output

__device__ __forceinline__ float lrelu(float x) { return x > 0.f ? x : 0.01f * x; }

// ================= setup: build Q_hat, B_hat, h =================
__global__ void setup_kernel(const float* __restrict__ L, const float* __restrict__ LP,
                             const float* __restrict__ LR, const float* __restrict__ A,
                             const float* __restrict__ Bm, const float* __restrict__ u0,
                             const float* __restrict__ s0) {
    __shared__ float sQx[144], sP[144], sR[16], sBp[9 * 48];
    __shared__ float sBh[NB * NU];
    __shared__ float sM[NB * NU];
    int tid = threadIdx.x;

    for (int idx = tid; idx < 144; idx += NT) {
        int i = idx / 12, j = idx % 12;
        int mn = i < j ? i : j;
        float a = 0.f, b = 0.f;
        for (int k = 0; k <= mn; k++) {
            a += L[i * 12 + k] * L[j * 12 + k];
            b += LP[i * 12 + k] * LP[j * 12 + k];
        }
        sQx[idx] = a + (i == j ? EPSF : 0.f);
        sP[idx]  = b + (i == j ? EPSF : 0.f);
    }
    for (int idx = tid; idx < 16; idx += NT) {
        int i = idx / 4, j = idx % 4;
        int mn = i < j ? i : j;
        float a = 0.f;
        for (int k = 0; k <= mn; k++) a += LR[i * 4 + k] * LR[j * 4 + k];
        sR[idx] = a + (i == j ? EPSF : 0.f);
    }
    if (tid < 48) sBp[tid] = Bm[tid];
    __syncthreads();

    for (int m = 1; m < 9; m++) {
        if (tid < 48) {
            int i = tid / 4, o = tid % 4;
            float v = 0.f;
            for (int k = 0; k < 12; k++) v += A[i * 12 + k] * sBp[(m - 1) * 48 + k * 4 + o];
            sBp[m * 48 + tid] = v;
        }
        __syncthreads();
    }

    for (int idx = tid; idx < NB * NU; idx += NT) {
        int row = idx / NU, col = idx % NU;
        int rb = row / 12, i = row % 12, cb = col / 4, o = col % 4;
        float v = (cb <= rb) ? sBp[(rb - cb) * 48 + i * 4 + o] : 0.f;
        sBh[idx] = v;
        g_B[idx] = v;
    }
    __syncthreads();

    for (int idx = tid; idx < NB * NU; idx += NT) {
        int row = idx / NU, col = idx % NU;
        int rb = row / 12, i = row % 12;
        const float* Qd = (rb < 8) ? sQx : sP;
        float a = 0.f;
        for (int k = 0; k < 12; k++) a += Qd[i * 12 + k] * sBh[(rb * 12 + k) * NU + col];
        sM[idx] = a;
    }
    __syncthreads();

    for (int idx = tid; idx < NU * NU; idx += NT) {
        int a_ = idx / NU, b_ = idx % NU;
        float v = (a_ / 4 == b_ / 4) ? sR[(a_ % 4) * 4 + (b_ % 4)] : 0.f;
        for (int r = 0; r < NB; r++) v += sBh[r * NU + a_] * sM[r * NU + b_];
        g_Q[idx] = v;
    }

    for (int j = tid; j < NINEQ; j += NT) {
        float v = s0[j];
        if (j < NU) v += u0[j];
        else {
            for (int i = 0; i < NU; i++) v += sBh[(j - NU) * NU + i] * u0[i];
        }
        g_h[j] = v;
    }
}

// ================= MLP =================
__global__ void mlp_kernel(const float* __restrict__ x, const float* __restrict__ W1,
                           const float* __restrict__ b1, const float* __restrict__ W2,
                           const float* __restrict__ b2) {
    __shared__ float hbuf[4][NHID];
    int warp = threadIdx.x >> 5, lane = threadIdx.x & 31;
    int row = blockIdx.x * 4 + warp;

    float xr[NIN];
#pragma unroll
    for (int c = 0; c < NIN; c++) xr[c] = x[row * NIN + c];

#pragma unroll
    for (int t = 0; t < NHID / 32; t++) {
        int j = lane + 32 * t;
        const float* w = W1 + j * NIN;
        float acc = b1[j];
#pragma unroll
        for (int c = 0; c < NIN; c++) acc += w[c] * xr[c];
        hbuf[warp][j] = lrelu(acc);
    }
    __syncwarp();

    for (int k = 0; k < NU; k++) {
        const float* w = W2 + k * NHID;
        float acc = 0.f;
#pragma unroll
        for (int t = 0; t < NHID / 32; t++) {
            int j = lane + 32 * t;
            acc += w[j] * hbuf[warp][j];
        }
#pragma unroll
        for (int o = 16; o; o >>= 1) acc += __shfl_xor_sync(0xffffffffu, acc, o);
        if (lane == 0) g_p[row * NU + k] = lrelu(acc + b2[k]);
    }
}

// ================= IPM solve, one CTA per batch item =================
__global__ void __launch_bounds__(NT) ipm_kernel(float* __restrict__ out) {
    __shared__ float sQ[NU * 41];
    __shared__ float sB[NB * 41];
    __shared__ float sH[NU * 41];
    __shared__ float sh_[NINEQ], sp_[NU], su[NU], ss[NINEQ], slam[NINEQ];
    __shared__ float srp[NINEQ], sv[NINEQ], sd[NINEQ], sds[NINEQ], sdl[NINEQ];
    __shared__ float srhs[NU], sdu[NU], sLd[NU];
    __shared__ float sredA[4], sredM[4];

    int tid = threadIdx.x;
    int lane = tid & 31, wid = tid >> 5;
    int b = blockIdx.x;

    for (int idx = tid; idx < NU * NU; idx += NT) sQ[(idx / NU) * 41 + idx % NU] = g_Q[idx];
    for (int idx = tid; idx < NB * NU; idx += NT) sB[(idx / NU) * 41 + idx % NU] = g_B[idx];
    for (int j = tid; j < NINEQ; j += NT) { sh_[j] = g_h[j]; ss[j] = 1.f; slam[j] = 1.f; }
    for (int i = tid; i < NU; i += NT) { sp_[i] = g_p[b * NU + i]; su[i] = 0.f; }
    __syncthreads();

    // ---- role mapping for H/rhs phase (fixed per thread) ----
    // tid 0..54   : H group A, lower block hb=tid, j in [0,54)
    // tid 64..118 : H group B, lower block hb=tid-64, j in [54,108), reg accum
    // tid 55..63 & 119..127 : rhs threads (ridx 0..17)
    int hb = -1, jlo = 0, ridx = -1;
    bool isB = false;
    if (tid < 55) { hb = tid; jlo = 0; }
    else if (tid >= 64 && tid < 119) { hb = tid - 64; jlo = 54; isB = true; }
    else ridx = (tid < 64) ? (tid - 55) : (tid - 110);
    int hbi = 0, hbk = 0;
    if (hb >= 0) {
        int t = hb, r = 0;
        while (t >= r + 1) { t -= r + 1; r++; }
        hbi = r; hbk = t;
    }

    for (int it = 0; it < IPM_ITERS; it++) {
        // ---- S0: d, rp, v (mu from previous iter's partials; mu0 = 1 exactly) ----
        float mu = (it == 0) ? 1.0f
                 : (sredM[0] + sredM[1] + sredM[2] + sredM[3]) * (1.0f / 148.0f);
        for (int j = tid; j < NINEQ; j += NT) {
            float sj = ss[j], lj = slam[j];
            float dj = lj / sj;
            sd[j] = dj;
            float rpj;
            if (j < NU) rpj = su[j];
            else {
                const float* br = sB + (j - NU) * 41;
                float a = 0.f;
#pragma unroll
                for (int i = 0; i < NU; i++) a += br[i] * su[i];
                rpj = a;
            }
            rpj += sj - sh_[j];
            srp[j] = rpj;
            sv[j] = SIGMA * mu / sj + dj * rpj;
        }
        __syncthreads();

        // ---- S1: H lower blocks (split j) + rhs ----
        float acc[4][4];
        if (hb >= 0) {
            if (!isB) {
#pragma unroll
                for (int a = 0; a < 4; a++)
#pragma unroll
                    for (int c = 0; c < 4; c++) {
                        int i = 4 * hbi + a, k = 4 * hbk + c;
                        acc[a][c] = sQ[i * 41 + k] + (i == k ? sd[i] : 0.f);
                    }
            } else {
#pragma unroll
                for (int a = 0; a < 4; a++)
#pragma unroll
                    for (int c = 0; c < 4; c++) acc[a][c] = 0.f;
            }
            for (int j = jlo; j < jlo + 54; j++) {
                const float* br = sB + j * 41;
                float dj = sd[NU + j];
                float ga[4], gb[4];
#pragma unroll
                for (int a = 0; a < 4; a++) ga[a] = dj * br[4 * hbi + a];
#pragma unroll
                for (int c = 0; c < 4; c++) gb[c] = br[4 * hbk + c];
#pragma unroll
                for (int a = 0; a < 4; a++)
#pragma unroll
                    for (int c = 0; c < 4; c++) acc[a][c] += ga[a] * gb[c];
            }
            if (!isB) {
#pragma unroll
                for (int a = 0; a < 4; a++)
#pragma unroll
                    for (int c = 0; c < 4; c++)
                        sH[(4 * hbi + a) * 41 + 4 * hbk + c] = acc[a][c];
            }
        } else {
            for (int i = ridx; i < NU; i += 18) {
                float a = sp_[i] + sv[i];
                const float* qr = sQ + i * 41;
#pragma unroll
                for (int k = 0; k < NU; k++) a += qr[k] * su[k];
                for (int j = 0; j < NB; j++) a += sv[NU + j] * sB[j * 41 + i];
                srhs[i] = -a;
            }
        }
        __syncthreads();

        // ---- S2: group B accumulates into sH ----
        if (isB) {
#pragma unroll
            for (int a = 0; a < 4; a++)
#pragma unroll
                for (int c = 0; c < 4; c++)
                    sH[(4 * hbi + a) * 41 + 4 * hbk + c] += acc[a][c];
        }
        __syncthreads();

        // ---- S3: blocked Cholesky (lower, panel=8) + triangular solves ----
        for (int p = 0; p < 5; p++) {
            int k0 = 8 * p;
            if (tid < 32) {
                // panel factor by warp 0
                for (int kk = 0; kk < 8; kk++) {
                    int k = k0 + kk;
                    float sq = sqrtf(sH[k * 41 + k]);
                    float inv = 1.0f / sq;
                    if (lane == 0) sLd[k] = sq;
                    int i0 = k + 1 + lane, i1 = i0 + 32;
                    float v0 = 0.f, v1 = 0.f;
                    if (i0 < NU) { v0 = sH[i0 * 41 + k] * inv; sH[i0 * 41 + k] = v0; }
                    if (i1 < NU) { v1 = sH[i1 * 41 + k] * inv; sH[i1 * 41 + k] = v1; }
                    __syncwarp();
                    for (int j = k + 1; j < k0 + 8; j++) {
                        float m = __shfl_sync(0xffffffffu, v0, j - k - 1);
                        if (i0 < NU && i0 >= j) sH[i0 * 41 + j] -= v0 * m;
                        if (i1 < NU)            sH[i1 * 41 + j] -= v1 * m;
                    }
                    __syncwarp();
                }
                if (p == 4) {
                    // triangular solves right here (in-warp ordering suffices)
                    float b0 = srhs[lane];
                    float b1 = (lane < 8) ? srhs[32 + lane] : 0.f;
                    for (int k = 0; k < NU; k++) {
                        float src = (k < 32) ? b0 : b1;
                        float yk = __shfl_sync(0xffffffffu, src, k & 31) / sLd[k];
                        if (k < 32) { if (lane == k) b0 = yk; }
                        else        { if (lane == k - 32) b1 = yk; }
                        if (lane > k) b0 -= sH[lane * 41 + k] * yk;
                        if (lane < 8 && 32 + lane > k) b1 -= sH[(32 + lane) * 41 + k] * yk;
                    }
                    for (int k = NU - 1; k >= 0; k--) {
                        float src = (k < 32) ? b0 : b1;
                        float xk = __shfl_sync(0xffffffffu, src, k & 31) / sLd[k];
                        if (k < 32) { if (lane == k) b0 = xk; }
                        else        { if (lane == k - 32) b1 = xk; }
                        if (lane < k) b0 -= sH[k * 41 + lane] * xk;
                        if (lane < 8 && 32 + lane < k) b1 -= sH[k * 41 + 32 + lane] * xk;
                    }
                    sdu[lane] = b0;
                    if (lane < 8) sdu[32 + lane] = b1;
                }
            }
            __syncthreads();
            if (p < 4) {
                // rank-8 trailing update, lower 4x4 blocks, all threads
                int base = k0 + 8;
                int nbk = (NU - base) >> 2;
                int cnt = nbk * (nbk + 1) / 2;
                if (tid < cnt) {
                    int t = tid, r = 0;
                    while (t >= r + 1) { t -= r + 1; r++; }
                    int c = t;
                    int ri = base + 4 * r, ci = base + 4 * c;
                    float a2[4][4];
#pragma unroll
                    for (int a = 0; a < 4; a++)
#pragma unroll
                        for (int cb = 0; cb < 4; cb++)
                            a2[a][cb] = sH[(ri + a) * 41 + ci + cb];
#pragma unroll
                    for (int kk = 0; kk < 8; kk++) {
                        float la[4], lb[4];
#pragma unroll
                        for (int a = 0; a < 4; a++) la[a] = sH[(ri + a) * 41 + k0 + kk];
#pragma unroll
                        for (int cb = 0; cb < 4; cb++) lb[cb] = sH[(ci + cb) * 41 + k0 + kk];
#pragma unroll
                        for (int a = 0; a < 4; a++)
#pragma unroll
                            for (int cb = 0; cb < 4; cb++)
                                a2[a][cb] -= la[a] * lb[cb];
                    }
#pragma unroll
                    for (int a = 0; a < 4; a++)
#pragma unroll
                        for (int cb = 0; cb < 4; cb++)
                            sH[(ri + a) * 41 + ci + cb] = a2[a][cb];
                }
                __syncthreads();
            }
        }

        // ---- S4: Gdu, ds, dlam, alpha partial mins ----
        float amin = BIGF;
        for (int j = tid; j < NINEQ; j += NT) {
            float gdu;
            if (j < NU) gdu = sdu[j];
            else {
                const float* br = sB + (j - NU) * 41;
                float a = 0.f;
#pragma unroll
                for (int i = 0; i < NU; i++) a += br[i] * sdu[i];
                gdu = a;
            }
            float dsj = -srp[j] - gdu;
            float dlj = sv[j] - slam[j] + sd[j] * gdu;
            sds[j] = dsj;
            sdl[j] = dlj;
            float a1 = (dsj < 0.f) ? -ss[j] / dsj : BIGF;
            float a2m = (dlj < 0.f) ? -slam[j] / dlj : BIGF;
            amin = fminf(amin, fminf(a1, a2m));
        }
#pragma unroll
        for (int o = 16; o; o >>= 1) amin = fminf(amin, __shfl_xor_sync(0xffffffffu, amin, o));
        if (lane == 0) sredA[wid] = amin;
        __syncthreads();

        // ---- S5: every thread finalizes alpha; update; mu partials ----
        float alpha = fminf(1.0f, 0.99f * fminf(fminf(sredA[0], sredA[1]),
                                                fminf(sredA[2], sredA[3])));
        float lsum = 0.f;
        for (int j = tid; j < NINEQ; j += NT) {
            float sn = ss[j] + alpha * sds[j];
            float ln = slam[j] + alpha * sdl[j];
            ss[j] = sn;
            slam[j] = ln;
            lsum += sn * ln;
        }
        if (tid < NU) su[tid] += alpha * sdu[tid];
#pragma unroll
        for (int o = 16; o; o >>= 1) lsum += __shfl_xor_sync(0xffffffffu, lsum, o);
        if (lane == 0) sredM[wid] = lsum;
        __syncthreads();
    }

    // ---- output: Q_value = 0.5 u'Qu + p'u ; u0 ----
    float part = 0.f;
    for (int i = tid; i < NU; i += NT) {
        const float* qr = sQ + i * 41;
        float qu = 0.f;
#pragma unroll
        for (int k = 0; k < NU; k++) qu += qr[k] * su[k];
        part += su[i] * (0.5f * qu + sp_[i]);
    }
#pragma unroll
    for (int o = 16; o; o >>= 1) part += __shfl_xor_sync(0xffffffffu, part, o);
    if (lane == 0) sredA[wid] = part;
    __syncthreads();
    if (tid == 0) {
        out[b] = sredA[0] + sredA[1] + sredA[2] + sredA[3];
        out[BATCH + b] = su[0];
    }
}

// ================= launch =================
extern "C" void kernel_launch(void* const* d_in, const int* in_sizes, int n_in,
                              void* d_out, int out_size) {
    const float* x  = (const float*)d_in[0];
    const float* W1 = (const float*)d_in[1];
    const float* b1 = (const float*)d_in[2];
    const float* W2 = (const float*)d_in[3];
    const float* b2 = (const float*)d_in[4];
    const float* L  = (const float*)d_in[5];
    const float* LP = (const float*)d_in[6];
    const float* LR = (const float*)d_in[7];
    const float* A  = (const float*)d_in[8];
    const float* Bm = (const float*)d_in[9];
    const float* u0 = (const float*)d_in[10];
    const float* s0 = (const float*)d_in[11];

    setup_kernel<<<1, NT>>>(L, LP, LR, A, Bm, u0, s0);
    mlp_kernel<<<BATCH / 4, NT>>>(x, W1, b1, W2, b2);
    ipm_kernel<<<BATCH, NT>>>((float*)d_out);
}

// round 3
// speedup vs baseline: 2.9204x; 1.7235x over previous
#include <cuda_runtime.h>
#include <math.h>

#define NIN   12
#define NOUT  4
#define NHID  512
#define NU    40
#define NB    108
#define NINEQ 148
#define BATCH 4096
#define IPM_ITERS 20
#define SIGMA 0.1f
#define BIGF  1000000000.0f
#define EPSF  0.0001f

#define WPB   8                 // problems (warps) per block
#define NTH   (32 * WPB)

// per-problem smem layout (floats)
#define P_H    0                // 40*41 = 1640
#define P_D    1640             // 148
#define P_V    1788             // 148
#define P_U    1936             // 40
#define P_RHS  1976             // 40
#define P_DU   2016             // 40
#define P_LD   2056             // 40
#define P_P    2096             // 40
#define PSTRIDE 2141            // padded (odd-ish)

#define SQ_OFF 0                // 40*41 = 1640
#define SB_OFF 1640             // 108*41 = 4428
#define PR_OFF 6068
#define SMEM_FLOATS (PR_OFF + WPB * PSTRIDE)
#define SMEM_BYTES  (SMEM_FLOATS * 4)

__device__ float g_Q[NU * NU];
__device__ float g_B[NB * NU];
__device__ float g_h[NINEQ];
__device__ float g_p[BATCH * NU];

__device__ __forceinline__ float lrelu(float x) { return x > 0.f ? x : 0.01f * x; }

// ================= setup =================
__global__ void setup_kernel(const float* __restrict__ L, const float* __restrict__ LP,
                             const float* __restrict__ LR, const float* __restrict__ A,
                             const float* __restrict__ Bm, const float* __restrict__ u0,
                             const float* __restrict__ s0) {
    __shared__ float sQx[144], sP[144], sR[16], sBp[9 * 48];
    __shared__ float sBh[NB * NU];
    __shared__ float sM[NB * NU];
    int tid = threadIdx.x;
    const int NTs = 128;

    for (int idx = tid; idx < 144; idx += NTs) {
        int i = idx / 12, j = idx % 12;
        int mn = i < j ? i : j;
        float a = 0.f, b = 0.f;
        for (int k = 0; k <= mn; k++) {
            a += L[i * 12 + k] * L[j * 12 + k];
            b += LP[i * 12 + k] * LP[j * 12 + k];
        }
        sQx[idx] = a + (i == j ? EPSF : 0.f);
        sP[idx]  = b + (i == j ? EPSF : 0.f);
    }
    for (int idx = tid; idx < 16; idx += NTs) {
        int i = idx / 4, j = idx % 4;
        int mn = i < j ? i : j;
        float a = 0.f;
        for (int k = 0; k <= mn; k++) a += LR[i * 4 + k] * LR[j * 4 + k];
        sR[idx] = a + (i == j ? EPSF : 0.f);
    }
    if (tid < 48) sBp[tid] = Bm[tid];
    __syncthreads();

    for (int m = 1; m < 9; m++) {
        if (tid < 48) {
            int i = tid / 4, o = tid % 4;
            float v = 0.f;
            for (int k = 0; k < 12; k++) v += A[i * 12 + k] * sBp[(m - 1) * 48 + k * 4 + o];
            sBp[m * 48 + tid] = v;
        }
        __syncthreads();
    }

    for (int idx = tid; idx < NB * NU; idx += NTs) {
        int row = idx / NU, col = idx % NU;
        int rb = row / 12, i = row % 12, cb = col / 4, o = col % 4;
        float v = (cb <= rb) ? sBp[(rb - cb) * 48 + i * 4 + o] : 0.f;
        sBh[idx] = v;
        g_B[idx] = v;
    }
    __syncthreads();

    for (int idx = tid; idx < NB * NU; idx += NTs) {
        int row = idx / NU, col = idx % NU;
        int rb = row / 12, i = row % 12;
        const float* Qd = (rb < 8) ? sQx : sP;
        float a = 0.f;
        for (int k = 0; k < 12; k++) a += Qd[i * 12 + k] * sBh[(rb * 12 + k) * NU + col];
        sM[idx] = a;
    }
    __syncthreads();

    for (int idx = tid; idx < NU * NU; idx += NTs) {
        int a_ = idx / NU, b_ = idx % NU;
        float v = (a_ / 4 == b_ / 4) ? sR[(a_ % 4) * 4 + (b_ % 4)] : 0.f;
        for (int r = 0; r < NB; r++) v += sBh[r * NU + a_] * sM[r * NU + b_];
        g_Q[idx] = v;
    }

    for (int j = tid; j < NINEQ; j += NTs) {
        float v = s0[j];
        if (j < NU) v += u0[j];
        else {
            for (int i = 0; i < NU; i++) v += sBh[(j - NU) * NU + i] * u0[i];
        }
        g_h[j] = v;
    }
}

// ================= MLP =================
__global__ void mlp_kernel(const float* __restrict__ x, const float* __restrict__ W1,
                           const float* __restrict__ b1, const float* __restrict__ W2,
                           const float* __restrict__ b2) {
    __shared__ float hbuf[4][NHID];
    int warp = threadIdx.x >> 5, lane = threadIdx.x & 31;
    int row = blockIdx.x * 4 + warp;

    float xr[NIN];
#pragma unroll
    for (int c = 0; c < NIN; c++) xr[c] = x[row * NIN + c];

#pragma unroll
    for (int t = 0; t < NHID / 32; t++) {
        int j = lane + 32 * t;
        const float* w = W1 + j * NIN;
        float acc = b1[j];
#pragma unroll
        for (int c = 0; c < NIN; c++) acc += w[c] * xr[c];
        hbuf[warp][j] = lrelu(acc);
    }
    __syncwarp();

    for (int k = 0; k < NU; k++) {
        const float* w = W2 + k * NHID;
        float acc = 0.f;
#pragma unroll
        for (int t = 0; t < NHID / 32; t++) {
            int j = lane + 32 * t;
            acc += w[j] * hbuf[warp][j];
        }
#pragma unroll
        for (int o = 16; o; o >>= 1) acc += __shfl_xor_sync(0xffffffffu, acc, o);
        if (lane == 0) g_p[row * NU + k] = lrelu(acc + b2[k]);
    }
}

// ================= IPM: one problem per WARP =================
__global__ void __launch_bounds__(NTH, 2) ipm_kernel(float* __restrict__ out) {
    extern __shared__ float sm[];
    float* sQ = sm + SQ_OFF;
    float* sB = sm + SB_OFF;

    int tid = threadIdx.x;
    int lane = tid & 31, wid = tid >> 5;
    int b = blockIdx.x * WPB + wid;

    // cooperative load of Q, B (row stride 40 -> 41)
    for (int idx = tid; idx < NU * NU; idx += NTH) sm[SQ_OFF + (idx / NU) * 41 + idx % NU] = g_Q[idx];
    for (int idx = tid; idx < NB * NU; idx += NTH) sm[SB_OFF + (idx / NU) * 41 + idx % NU] = g_B[idx];
    __syncthreads();

    float* Pb = sm + PR_OFF + wid * PSTRIDE;
    float* pH = Pb + P_H;
    float* pD = Pb + P_D;
    float* pV = Pb + P_V;
    float* pU = Pb + P_U;
    float* pR = Pb + P_RHS;
    float* pDU = Pb + P_DU;
    float* pLD = Pb + P_LD;
    float* pP = Pb + P_P;

    // per-lane register state: j = lane + 32*t, t = 0..4 (t=4 valid iff lane<20)
    float rs[5], rlam[5], rh[5], rrp[5], rv[5], rd[5], rds[5], rdl[5];
#pragma unroll
    for (int t = 0; t < 5; t++) {
        int j = lane + 32 * t;
        bool ok = (j < NINEQ);
        rs[t] = 1.f; rlam[t] = 1.f;
        rh[t] = ok ? g_h[j] : 0.f;
    }
    if (lane < NU) pU[lane] = 0.f;
    if (lane < 8) pU[32 + lane] = 0.f;
    if (lane < NU) pP[lane] = g_p[b * NU + lane];
    if (lane < 8) pP[32 + lane] = g_p[b * NU + 32 + lane];

    // H lower-triangle 4x4 block assignment: blk0 = lane, blk1 = lane+32 (<55)
    int bi0 = 0, bk0 = 0, bi1 = 0, bk1 = 0;
    {
        int t = lane, r = 0;
        while (t > r) { t -= r + 1; r++; }
        bi0 = r; bk0 = t;
        t = lane + 32; r = 0;
        if (t < 55) { while (t > r) { t -= r + 1; r++; } bi1 = r; bk1 = t; }
    }
    bool has1 = (lane < 23);

    float mu = 1.0f;
    __syncwarp();

    for (int it = 0; it < IPM_ITERS; it++) {
        // ---- S0: d, rp, v ----
#pragma unroll
        for (int t = 0; t < 5; t++) {
            int j = lane + 32 * t;
            if (j < NINEQ) {
                float dj = rlam[t] / rs[t];
                rd[t] = dj;
                pD[j] = dj;
                float rpj;
                if (j < NU) rpj = pU[j];
                else {
                    const float* br = sB + (j - NU) * 41;
                    float a = 0.f;
#pragma unroll
                    for (int i = 0; i < NU; i++) a += br[i] * pU[i];
                    rpj = a;
                }
                rpj += rs[t] - rh[t];
                rrp[t] = rpj;
                float vj = SIGMA * mu / rs[t] + dj * rpj;
                rv[t] = vj;
                pV[j] = vj;
            }
        }
        __syncwarp();

        // ---- S1: H lower blocks (pass per block) ----
        for (int pass = 0; pass < 2; pass++) {
            if (pass == 1 && !has1) break;
            int bi = pass ? bi1 : bi0, bk = pass ? bk1 : bk0;
            float acc[4][4];
#pragma unroll
            for (int a = 0; a < 4; a++)
#pragma unroll
                for (int c = 0; c < 4; c++) {
                    int i = 4 * bi + a, k = 4 * bk + c;
                    acc[a][c] = sQ[i * 41 + k] + (i == k ? pD[i] : 0.f);
                }
            for (int j = 0; j < NB; j++) {
                const float* br = sB + j * 41;
                float dj = pD[NU + j];
                float ga[4], gb[4];
#pragma unroll
                for (int a = 0; a < 4; a++) ga[a] = dj * br[4 * bi + a];
#pragma unroll
                for (int c = 0; c < 4; c++) gb[c] = br[4 * bk + c];
#pragma unroll
                for (int a = 0; a < 4; a++)
#pragma unroll
                    for (int c = 0; c < 4; c++) acc[a][c] += ga[a] * gb[c];
            }
#pragma unroll
            for (int a = 0; a < 4; a++)
#pragma unroll
                for (int c = 0; c < 4; c++)
                    pH[(4 * bi + a) * 41 + 4 * bk + c] = acc[a][c];
        }

        // ---- rhs = -(Qu + p + v[:40] + B^T v[40:]) ----
        {
            float a0 = pP[lane] + pV[lane];
            float a1 = (lane < 8) ? (pP[32 + lane] + pV[32 + lane]) : 0.f;
            const float* q0 = sQ + lane * 41;
            const float* q1 = sQ + (32 + lane) * 41;
#pragma unroll
            for (int k = 0; k < NU; k++) {
                float uk = pU[k];
                a0 += q0[k] * uk;
                if (lane < 8) a1 += q1[k] * uk;
            }
            for (int j = 0; j < NB; j++) {
                float vj = pV[NU + j];
                const float* br = sB + j * 41;
                a0 += vj * br[lane];
                if (lane < 8) a1 += vj * br[32 + lane];
            }
            pR[lane] = -a0;
            if (lane < 8) pR[32 + lane] = -a1;
        }
        __syncwarp();

        // ---- S3: warp-local blocked Cholesky (panel=8) ----
        for (int p = 0; p < 5; p++) {
            int k0 = 8 * p;
            for (int kk = 0; kk < 8; kk++) {
                int k = k0 + kk;
                float sq = sqrtf(pH[k * 41 + k]);
                float inv = 1.0f / sq;
                if (lane == 0) pLD[k] = sq;
                int i0 = k + 1 + lane, i1 = i0 + 32;
                float v0 = 0.f, v1 = 0.f;
                if (i0 < NU) { v0 = pH[i0 * 41 + k] * inv; pH[i0 * 41 + k] = v0; }
                if (i1 < NU) { v1 = pH[i1 * 41 + k] * inv; pH[i1 * 41 + k] = v1; }
                __syncwarp();
                for (int j = k + 1; j < k0 + 8; j++) {
                    float m = __shfl_sync(0xffffffffu, v0, j - k - 1);
                    if (i0 < NU && i0 >= j) pH[i0 * 41 + j] -= v0 * m;
                    if (i1 < NU)            pH[i1 * 41 + j] -= v1 * m;
                }
                __syncwarp();
            }
            if (p < 4) {
                int base = k0 + 8;
                int nbk = (NU - base) >> 2;
                int cnt = nbk * (nbk + 1) / 2;
                for (int bb = lane; bb < cnt; bb += 32) {
                    int t = bb, r = 0;
                    while (t > r) { t -= r + 1; r++; }
                    int c = t;
                    int ri = base + 4 * r, ci = base + 4 * c;
                    float a2[4][4];
#pragma unroll
                    for (int a = 0; a < 4; a++)
#pragma unroll
                        for (int cb = 0; cb < 4; cb++)
                            a2[a][cb] = pH[(ri + a) * 41 + ci + cb];
#pragma unroll
                    for (int kk = 0; kk < 8; kk++) {
                        float la[4], lb[4];
#pragma unroll
                        for (int a = 0; a < 4; a++) la[a] = pH[(ri + a) * 41 + k0 + kk];
#pragma unroll
                        for (int cb = 0; cb < 4; cb++) lb[cb] = pH[(ci + cb) * 41 + k0 + kk];
#pragma unroll
                        for (int a = 0; a < 4; a++)
#pragma unroll
                            for (int cb = 0; cb < 4; cb++)
                                a2[a][cb] -= la[a] * lb[cb];
                    }
#pragma unroll
                    for (int a = 0; a < 4; a++)
#pragma unroll
                        for (int cb = 0; cb < 4; cb++)
                            pH[(ri + a) * 41 + ci + cb] = a2[a][cb];
                }
                __syncwarp();
            }
        }

        // ---- triangular solves (warp-local shuffles) ----
        {
            float b0 = pR[lane];
            float b1 = (lane < 8) ? pR[32 + lane] : 0.f;
            for (int k = 0; k < NU; k++) {
                float src = (k < 32) ? b0 : b1;
                float yk = __shfl_sync(0xffffffffu, src, k & 31) / pLD[k];
                if (k < 32) { if (lane == k) b0 = yk; }
                else        { if (lane == k - 32) b1 = yk; }
                if (lane > k) b0 -= pH[lane * 41 + k] * yk;
                if (lane < 8 && 32 + lane > k) b1 -= pH[(32 + lane) * 41 + k] * yk;
            }
            for (int k = NU - 1; k >= 0; k--) {
                float src = (k < 32) ? b0 : b1;
                float xk = __shfl_sync(0xffffffffu, src, k & 31) / pLD[k];
                if (k < 32) { if (lane == k) b0 = xk; }
                else        { if (lane == k - 32) b1 = xk; }
                if (lane < k) b0 -= pH[k * 41 + lane] * xk;
                if (lane < 8 && 32 + lane < k) b1 -= pH[k * 41 + 32 + lane] * xk;
            }
            pDU[lane] = b0;
            if (lane < 8) pDU[32 + lane] = b1;
        }
        __syncwarp();

        // ---- S4: ds, dlam, alpha ----
        float amin = BIGF;
#pragma unroll
        for (int t = 0; t < 5; t++) {
            int j = lane + 32 * t;
            if (j < NINEQ) {
                float gdu;
                if (j < NU) gdu = pDU[j];
                else {
                    const float* br = sB + (j - NU) * 41;
                    float a = 0.f;
#pragma unroll
                    for (int i = 0; i < NU; i++) a += br[i] * pDU[i];
                    gdu = a;
                }
                float dsj = -rrp[t] - gdu;
                float dlj = rv[t] - rlam[t] + rd[t] * gdu;
                rds[t] = dsj;
                rdl[t] = dlj;
                float a1 = (dsj < 0.f) ? -rs[t] / dsj : BIGF;
                float a2 = (dlj < 0.f) ? -rlam[t] / dlj : BIGF;
                amin = fminf(amin, fminf(a1, a2));
            }
        }
#pragma unroll
        for (int o = 16; o; o >>= 1) amin = fminf(amin, __shfl_xor_sync(0xffffffffu, amin, o));
        float alpha = fminf(1.0f, 0.99f * amin);

        // ---- S5: update + mu for next iter ----
        float lsum = 0.f;
#pragma unroll
        for (int t = 0; t < 5; t++) {
            int j = lane + 32 * t;
            if (j < NINEQ) {
                rs[t] += alpha * rds[t];
                rlam[t] += alpha * rdl[t];
                lsum += rs[t] * rlam[t];
            }
        }
#pragma unroll
        for (int o = 16; o; o >>= 1) lsum += __shfl_xor_sync(0xffffffffu, lsum, o);
        mu = lsum * (1.0f / 148.0f);

        pU[lane] += alpha * pDU[lane];
        if (lane < 8) pU[32 + lane] += alpha * pDU[32 + lane];
        __syncwarp();
    }

    // ---- output ----
    float part;
    {
        const float* q0 = sQ + lane * 41;
        const float* q1 = sQ + (32 + lane) * 41;
        float qu0 = 0.f, qu1 = 0.f;
#pragma unroll
        for (int k = 0; k < NU; k++) {
            float uk = pU[k];
            qu0 += q0[k] * uk;
            if (lane < 8) qu1 += q1[k] * uk;
        }
        part = pU[lane] * (0.5f * qu0 + pP[lane]);
        if (lane < 8) part += pU[32 + lane] * (0.5f * qu1 + pP[32 + lane]);
    }
#pragma unroll
    for (int o = 16; o; o >>= 1) part += __shfl_xor_sync(0xffffffffu, part, o);
    if (lane == 0) {
        out[b] = part;
        out[BATCH + b] = pU[0];
    }
}

// ================= launch =================
extern "C" void kernel_launch(void* const* d_in, const int* in_sizes, int n_in,
                              void* d_out, int out_size) {
    const float* x  = (const float*)d_in[0];
    const float* W1 = (const float*)d_in[1];
    const float* b1 = (const float*)d_in[2];
    const float* W2 = (const float*)d_in[3];
    const float* b2 = (const float*)d_in[4];
    const float* L  = (const float*)d_in[5];
    const float* LP = (const float*)d_in[6];
    const float* LR = (const float*)d_in[7];
    const float* A  = (const float*)d_in[8];
    const float* Bm = (const float*)d_in[9];
    const float* u0 = (const float*)d_in[10];
    const float* s0 = (const float*)d_in[11];

    cudaFuncSetAttribute(ipm_kernel, cudaFuncAttributeMaxDynamicSharedMemorySize, SMEM_BYTES);

    setup_kernel<<<1, 128>>>(L, LP, LR, A, Bm, u0, s0);
    mlp_kernel<<<BATCH / 4, 128>>>(x, W1, b1, W2, b2);
    ipm_kernel<<<BATCH / WPB, NTH, SMEM_BYTES>>>((float*)d_out);
}

// round 4
// speedup vs baseline: 3.5357x; 1.2107x over previous
#include <cuda_runtime.h>
#include <math.h>

#define NIN   12
#define NOUT  4
#define NHID  512
#define NU    40
#define NB    108
#define NINEQ 148
#define BATCH 4096
#define IPM_ITERS 20
#define SIGMA 0.1f
#define BIGF  1000000000.0f
#define EPSF  0.0001f

#define WPB   8
#define NTH   (32 * WPB)

// shared Q/B: stride 44 (float4-aligned rows)
#define SQ_OFF 0                        // 40*44 = 1760
#define SB_OFF 1760                     // 108*44 = 4752
#define PR_OFF 6512

// per-problem layout (floats). pH uses stride 41 (column-access friendly).
#define P_H    0                        // 40*41 = 1640
#define P_D    1640                     // 148
#define P_V    1788                     // 148
#define P_U    1936                     // 40  (16B aligned)
#define P_RHS  1976                     // 40
#define P_DU   2016                     // 40  (16B aligned)
#define P_LDI  2056                     // 40  reciprocal diag
#define P_P    2096                     // 40
#define PSTRIDE 2144

#define SMEM_FLOATS (PR_OFF + WPB * PSTRIDE)
#define SMEM_BYTES  (SMEM_FLOATS * 4)

__device__ float g_Q[NU * NU];
__device__ float g_B[NB * NU];
__device__ float g_h[NINEQ];
__device__ float g_p[BATCH * NU];

__device__ __forceinline__ float lrelu(float x) { return x > 0.f ? x : 0.01f * x; }

// ================= setup =================
__global__ void setup_kernel(const float* __restrict__ L, const float* __restrict__ LP,
                             const float* __restrict__ LR, const float* __restrict__ A,
                             const float* __restrict__ Bm, const float* __restrict__ u0,
                             const float* __restrict__ s0) {
    __shared__ float sQx[144], sP[144], sR[16], sBp[9 * 48];
    __shared__ float sBh[NB * NU];
    __shared__ float sM[NB * NU];
    int tid = threadIdx.x;
    const int NTs = 128;

    for (int idx = tid; idx < 144; idx += NTs) {
        int i = idx / 12, j = idx % 12;
        int mn = i < j ? i : j;
        float a = 0.f, b = 0.f;
        for (int k = 0; k <= mn; k++) {
            a += L[i * 12 + k] * L[j * 12 + k];
            b += LP[i * 12 + k] * LP[j * 12 + k];
        }
        sQx[idx] = a + (i == j ? EPSF : 0.f);
        sP[idx]  = b + (i == j ? EPSF : 0.f);
    }
    for (int idx = tid; idx < 16; idx += NTs) {
        int i = idx / 4, j = idx % 4;
        int mn = i < j ? i : j;
        float a = 0.f;
        for (int k = 0; k <= mn; k++) a += LR[i * 4 + k] * LR[j * 4 + k];
        sR[idx] = a + (i == j ? EPSF : 0.f);
    }
    if (tid < 48) sBp[tid] = Bm[tid];
    __syncthreads();

    for (int m = 1; m < 9; m++) {
        if (tid < 48) {
            int i = tid / 4, o = tid % 4;
            float v = 0.f;
            for (int k = 0; k < 12; k++) v += A[i * 12 + k] * sBp[(m - 1) * 48 + k * 4 + o];
            sBp[m * 48 + tid] = v;
        }
        __syncthreads();
    }

    for (int idx = tid; idx < NB * NU; idx += NTs) {
        int row = idx / NU, col = idx % NU;
        int rb = row / 12, i = row % 12, cb = col / 4, o = col % 4;
        float v = (cb <= rb) ? sBp[(rb - cb) * 48 + i * 4 + o] : 0.f;
        sBh[idx] = v;
        g_B[idx] = v;
    }
    __syncthreads();

    for (int idx = tid; idx < NB * NU; idx += NTs) {
        int row = idx / NU, col = idx % NU;
        int rb = row / 12, i = row % 12;
        const float* Qd = (rb < 8) ? sQx : sP;
        float a = 0.f;
        for (int k = 0; k < 12; k++) a += Qd[i * 12 + k] * sBh[(rb * 12 + k) * NU + col];
        sM[idx] = a;
    }
    __syncthreads();

    for (int idx = tid; idx < NU * NU; idx += NTs) {
        int a_ = idx / NU, b_ = idx % NU;
        float v = (a_ / 4 == b_ / 4) ? sR[(a_ % 4) * 4 + (b_ % 4)] : 0.f;
        for (int r = 0; r < NB; r++) v += sBh[r * NU + a_] * sM[r * NU + b_];
        g_Q[idx] = v;
    }

    for (int j = tid; j < NINEQ; j += NTs) {
        float v = s0[j];
        if (j < NU) v += u0[j];
        else {
            for (int i = 0; i < NU; i++) v += sBh[(j - NU) * NU + i] * u0[i];
        }
        g_h[j] = v;
    }
}

// ================= MLP =================
__global__ void mlp_kernel(const float* __restrict__ x, const float* __restrict__ W1,
                           const float* __restrict__ b1, const float* __restrict__ W2,
                           const float* __restrict__ b2) {
    __shared__ float hbuf[4][NHID];
    int warp = threadIdx.x >> 5, lane = threadIdx.x & 31;
    int row = blockIdx.x * 4 + warp;

    float xr[NIN];
#pragma unroll
    for (int c = 0; c < NIN; c++) xr[c] = x[row * NIN + c];

#pragma unroll
    for (int t = 0; t < NHID / 32; t++) {
        int j = lane + 32 * t;
        const float* w = W1 + j * NIN;
        float acc = b1[j];
#pragma unroll
        for (int c = 0; c < NIN; c++) acc += w[c] * xr[c];
        hbuf[warp][j] = lrelu(acc);
    }
    __syncwarp();

    for (int k = 0; k < NU; k++) {
        const float* w = W2 + k * NHID;
        float acc = 0.f;
#pragma unroll
        for (int t = 0; t < NHID / 32; t++) {
            int j = lane + 32 * t;
            acc += w[j] * hbuf[warp][j];
        }
#pragma unroll
        for (int o = 16; o; o >>= 1) acc += __shfl_xor_sync(0xffffffffu, acc, o);
        if (lane == 0) g_p[row * NU + k] = lrelu(acc + b2[k]);
    }
}

// ================= IPM: one problem per warp =================
__global__ void __launch_bounds__(NTH, 2) ipm_kernel(float* __restrict__ out) {
    extern __shared__ float sm[];
    float* sQ = sm + SQ_OFF;   // stride 44
    float* sB = sm + SB_OFF;   // stride 44

    int tid = threadIdx.x;
    int lane = tid & 31, wid = tid >> 5;
    int b = blockIdx.x * WPB + wid;

    for (int idx = tid; idx < NU * NU; idx += NTH) sQ[(idx / NU) * 44 + idx % NU] = g_Q[idx];
    for (int idx = tid; idx < NB * NU; idx += NTH) sB[(idx / NU) * 44 + idx % NU] = g_B[idx];
    __syncthreads();

    float* Pb  = sm + PR_OFF + wid * PSTRIDE;
    float* pH  = Pb + P_H;     // stride 41
    float* pD  = Pb + P_D;
    float* pV  = Pb + P_V;
    float* pU  = Pb + P_U;
    float* pR  = Pb + P_RHS;
    float* pDU = Pb + P_DU;
    float* pLi = Pb + P_LDI;
    float* pP  = Pb + P_P;

    // per-lane register state: j = lane + 32*t
    float rs[5], rlam[5], rh[5], rrp[5], rv[5], rd[5], rds[5], rdl[5];
#pragma unroll
    for (int t = 0; t < 5; t++) {
        int j = lane + 32 * t;
        rs[t] = 1.f; rlam[t] = 1.f;
        rh[t] = (j < NINEQ) ? g_h[j] : 0.f;
    }
    if (lane < NU) { pU[lane] = 0.f; pP[lane] = g_p[b * NU + lane]; }
    if (lane < 8)  { pU[32 + lane] = 0.f; pP[32 + lane] = g_p[b * NU + 32 + lane]; }

    // paired-block assignment: 25 pair-lanes + 5 single-lanes (+2 idle)
    int bi = 0, bkA = 0, bkB = 0;
    bool hasB = false, active = false;
    {
        int idx = 0;
        for (int r = 0; r < 10; r++) {
            int np = (r + 1) / 2;
            for (int q = 0; q < np; q++) {
                if (idx == lane) { bi = r; bkA = 2 * q; bkB = 2 * q + 1; hasB = true; active = true; }
                idx++;
            }
        }
        for (int r = 0; r < 10; r += 2) {
            if (idx == lane) { bi = r; bkA = r; bkB = r; hasB = false; active = true; }
            idx++;
        }
    }

    float mu = 1.0f;
    __syncwarp();

    for (int it = 0; it < IPM_ITERS; it++) {
        // ---- S0: d, rp, v ----
#pragma unroll
        for (int t = 0; t < 5; t++) {
            int j = lane + 32 * t;
            if (j < NINEQ) {
                float rinv = 1.0f / rs[t];
                float dj = rlam[t] * rinv;
                rd[t] = dj;
                pD[j] = dj;
                float rpj;
                if (j < NU) rpj = pU[j];
                else {
                    const float4* br4 = (const float4*)(sB + (j - NU) * 44);
                    const float4* u4  = (const float4*)pU;
                    float a = 0.f;
#pragma unroll
                    for (int q = 0; q < 10; q++) {
                        float4 bv = br4[q], uv = u4[q];
                        a += bv.x * uv.x + bv.y * uv.y + bv.z * uv.z + bv.w * uv.w;
                    }
                    rpj = a;
                }
                rpj += rs[t] - rh[t];
                rrp[t] = rpj;
                float vj = SIGMA * mu * rinv + dj * rpj;
                rv[t] = vj;
                pV[j] = vj;
            }
        }
        __syncwarp();

        // ---- S1: H (paired blocks) ----
        {
            float acc0[4][4], acc1[4][4];
            const float4* qa0 = (const float4*)(sQ + (4 * bi) * 44 + 4 * bkA);
            const float4* qa1 = (const float4*)(sQ + (4 * bi) * 44 + 4 * bkB);
#pragma unroll
            for (int a = 0; a < 4; a++) {
                float4 v0 = *(const float4*)((const float*)qa0 + a * 44);
                acc0[a][0] = v0.x; acc0[a][1] = v0.y; acc0[a][2] = v0.z; acc0[a][3] = v0.w;
                float4 v1 = *(const float4*)((const float*)qa1 + a * 44);
                acc1[a][0] = v1.x; acc1[a][1] = v1.y; acc1[a][2] = v1.z; acc1[a][3] = v1.w;
            }
            if (bi == bkA) {
#pragma unroll
                for (int a = 0; a < 4; a++) acc0[a][a] += pD[4 * bi + a];
            }
            if (bi == bkB) {
#pragma unroll
                for (int a = 0; a < 4; a++) acc1[a][a] += pD[4 * bi + a];
            }
#pragma unroll 2
            for (int j = 0; j < NB; j++) {
                float dj = pD[NU + j];
                const float* br = sB + j * 44;
                float4 gav = *(const float4*)(br + 4 * bi);
                float4 g0  = *(const float4*)(br + 4 * bkA);
                float4 g1  = *(const float4*)(br + 4 * bkB);
                float sa[4];
                sa[0] = dj * gav.x; sa[1] = dj * gav.y; sa[2] = dj * gav.z; sa[3] = dj * gav.w;
                float gb0[4] = {g0.x, g0.y, g0.z, g0.w};
                float gb1[4] = {g1.x, g1.y, g1.z, g1.w};
#pragma unroll
                for (int a = 0; a < 4; a++)
#pragma unroll
                    for (int c = 0; c < 4; c++) {
                        acc0[a][c] += sa[a] * gb0[c];
                        acc1[a][c] += sa[a] * gb1[c];
                    }
            }
            if (active) {
#pragma unroll
                for (int a = 0; a < 4; a++)
#pragma unroll
                    for (int c = 0; c < 4; c++)
                        pH[(4 * bi + a) * 41 + 4 * bkA + c] = acc0[a][c];
                if (hasB) {
#pragma unroll
                    for (int a = 0; a < 4; a++)
#pragma unroll
                        for (int c = 0; c < 4; c++)
                            pH[(4 * bi + a) * 41 + 4 * bkB + c] = acc1[a][c];
                }
            }
        }

        // ---- rhs = -(Qu + p + v[:40] + B^T v[40:]) ----
        {
            float a0 = pP[lane] + pV[lane];
            float a1 = (lane < 8) ? (pP[32 + lane] + pV[32 + lane]) : 0.f;
            const float4* q0 = (const float4*)(sQ + lane * 44);
            const float4* q1 = (const float4*)(sQ + (32 + lane) * 44);
            const float4* u4 = (const float4*)pU;
#pragma unroll
            for (int q = 0; q < 10; q++) {
                float4 uv = u4[q];
                float4 qv0 = q0[q];
                a0 += qv0.x * uv.x + qv0.y * uv.y + qv0.z * uv.z + qv0.w * uv.w;
                if (lane < 8) {
                    float4 qv1 = q1[q];
                    a1 += qv1.x * uv.x + qv1.y * uv.y + qv1.z * uv.z + qv1.w * uv.w;
                }
            }
#pragma unroll 2
            for (int j = 0; j < NB; j++) {
                float vj = pV[NU + j];
                const float* br = sB + j * 44;
                a0 += vj * br[lane];
                if (lane < 8) a1 += vj * br[32 + lane];
            }
            pR[lane] = -a0;
            if (lane < 8) pR[32 + lane] = -a1;
        }
        __syncwarp();

        // ---- S3: warp-local blocked Cholesky (panel=8) ----
        for (int p = 0; p < 5; p++) {
            int k0 = 8 * p;
            for (int kk = 0; kk < 8; kk++) {
                int k = k0 + kk;
                float hkk = pH[k * 41 + k];
                float inv = rsqrtf(hkk);
                inv = inv * (1.5f - 0.5f * hkk * inv * inv);  // Newton refine
                if (lane == 0) pLi[k] = inv;
                int i0 = k + 1 + lane, i1 = i0 + 32;
                float v0 = 0.f, v1 = 0.f;
                if (i0 < NU) { v0 = pH[i0 * 41 + k] * inv; pH[i0 * 41 + k] = v0; }
                if (i1 < NU) { v1 = pH[i1 * 41 + k] * inv; pH[i1 * 41 + k] = v1; }
                __syncwarp();
                for (int j = k + 1; j < k0 + 8; j++) {
                    float m = __shfl_sync(0xffffffffu, v0, j - k - 1);
                    if (i0 < NU && i0 >= j) pH[i0 * 41 + j] -= v0 * m;
                    if (i1 < NU)            pH[i1 * 41 + j] -= v1 * m;
                }
                __syncwarp();
            }
            if (p < 4) {
                int base = k0 + 8;
                int nbk = (NU - base) >> 2;
                int cnt = nbk * (nbk + 1) / 2;
                for (int bb = lane; bb < cnt; bb += 32) {
                    int t = bb, r = 0;
                    while (t > r) { t -= r + 1; r++; }
                    int c = t;
                    int ri = base + 4 * r, ci = base + 4 * c;
                    float a2[4][4];
#pragma unroll
                    for (int a = 0; a < 4; a++)
#pragma unroll
                        for (int cb = 0; cb < 4; cb++)
                            a2[a][cb] = pH[(ri + a) * 41 + ci + cb];
#pragma unroll
                    for (int kk = 0; kk < 8; kk++) {
                        float la[4], lb[4];
#pragma unroll
                        for (int a = 0; a < 4; a++) la[a] = pH[(ri + a) * 41 + k0 + kk];
#pragma unroll
                        for (int cb = 0; cb < 4; cb++) lb[cb] = pH[(ci + cb) * 41 + k0 + kk];
#pragma unroll
                        for (int a = 0; a < 4; a++)
#pragma unroll
                            for (int cb = 0; cb < 4; cb++)
                                a2[a][cb] -= la[a] * lb[cb];
                    }
#pragma unroll
                    for (int a = 0; a < 4; a++)
#pragma unroll
                        for (int cb = 0; cb < 4; cb++)
                            pH[(ri + a) * 41 + ci + cb] = a2[a][cb];
                }
                __syncwarp();
            }
        }

        // ---- triangular solves (multiply by reciprocal diag) ----
        {
            float b0 = pR[lane];
            float b1 = (lane < 8) ? pR[32 + lane] : 0.f;
            for (int k = 0; k < NU; k++) {
                float src = (k < 32) ? b0 : b1;
                float yk = __shfl_sync(0xffffffffu, src, k & 31) * pLi[k];
                if (k < 32) { if (lane == k) b0 = yk; }
                else        { if (lane == k - 32) b1 = yk; }
                if (lane > k) b0 -= pH[lane * 41 + k] * yk;
                if (lane < 8 && 32 + lane > k) b1 -= pH[(32 + lane) * 41 + k] * yk;
            }
            for (int k = NU - 1; k >= 0; k--) {
                float src = (k < 32) ? b0 : b1;
                float xk = __shfl_sync(0xffffffffu, src, k & 31) * pLi[k];
                if (k < 32) { if (lane == k) b0 = xk; }
                else        { if (lane == k - 32) b1 = xk; }
                if (lane < k) b0 -= pH[k * 41 + lane] * xk;
                if (lane < 8 && 32 + lane < k) b1 -= pH[k * 41 + 32 + lane] * xk;
            }
            pDU[lane] = b0;
            if (lane < 8) pDU[32 + lane] = b1;
        }
        __syncwarp();

        // ---- S4: ds, dlam, alpha ----
        float amin = BIGF;
#pragma unroll
        for (int t = 0; t < 5; t++) {
            int j = lane + 32 * t;
            if (j < NINEQ) {
                float gdu;
                if (j < NU) gdu = pDU[j];
                else {
                    const float4* br4 = (const float4*)(sB + (j - NU) * 44);
                    const float4* d4  = (const float4*)pDU;
                    float a = 0.f;
#pragma unroll
                    for (int q = 0; q < 10; q++) {
                        float4 bv = br4[q], dv = d4[q];
                        a += bv.x * dv.x + bv.y * dv.y + bv.z * dv.z + bv.w * dv.w;
                    }
                    gdu = a;
                }
                float dsj = -rrp[t] - gdu;
                float dlj = rv[t] - rlam[t] + rd[t] * gdu;
                rds[t] = dsj;
                rdl[t] = dlj;
                float a1 = (dsj < 0.f) ? -rs[t] / dsj : BIGF;
                float a2 = (dlj < 0.f) ? -rlam[t] / dlj : BIGF;
                amin = fminf(amin, fminf(a1, a2));
            }
        }
#pragma unroll
        for (int o = 16; o; o >>= 1) amin = fminf(amin, __shfl_xor_sync(0xffffffffu, amin, o));
        float alpha = fminf(1.0f, 0.99f * amin);

        // ---- S5: update + mu ----
        float lsum = 0.f;
#pragma unroll
        for (int t = 0; t < 5; t++) {
            int j = lane + 32 * t;
            if (j < NINEQ) {
                rs[t] += alpha * rds[t];
                rlam[t] += alpha * rdl[t];
                lsum += rs[t] * rlam[t];
            }
        }
#pragma unroll
        for (int o = 16; o; o >>= 1) lsum += __shfl_xor_sync(0xffffffffu, lsum, o);
        mu = lsum * (1.0f / 148.0f);

        pU[lane] += alpha * pDU[lane];
        if (lane < 8) pU[32 + lane] += alpha * pDU[32 + lane];
        __syncwarp();
    }

    // ---- output ----
    float part;
    {
        const float4* q0 = (const float4*)(sQ + lane * 44);
        const float4* q1 = (const float4*)(sQ + (32 + lane) * 44);
        const float4* u4 = (const float4*)pU;
        float qu0 = 0.f, qu1 = 0.f;
#pragma unroll
        for (int q = 0; q < 10; q++) {
            float4 uv = u4[q];
            float4 qv0 = q0[q];
            qu0 += qv0.x * uv.x + qv0.y * uv.y + qv0.z * uv.z + qv0.w * uv.w;
            if (lane < 8) {
                float4 qv1 = q1[q];
                qu1 += qv1.x * uv.x + qv1.y * uv.y + qv1.z * uv.z + qv1.w * uv.w;
            }
        }
        part = pU[lane] * (0.5f * qu0 + pP[lane]);
        if (lane < 8) part += pU[32 + lane] * (0.5f * qu1 + pP[32 + lane]);
    }
#pragma unroll
    for (int o = 16; o; o >>= 1) part += __shfl_xor_sync(0xffffffffu, part, o);
    if (lane == 0) {
        out[b] = part;
        out[BATCH + b] = pU[0];
    }
}

// ================= launch =================
extern "C" void kernel_launch(void* const* d_in, const int* in_sizes, int n_in,
                              void* d_out, int out_size) {
    const float* x  = (const float*)d_in[0];
    const float* W1 = (const float*)d_in[1];
    const float* b1 = (const float*)d_in[2];
    const float* W2 = (const float*)d_in[3];
    const float* b2 = (const float*)d_in[4];
    const float* L  = (const float*)d_in[5];
    const float* LP = (const float*)d_in[6];
    const float* LR = (const float*)d_in[7];
    const float* A  = (const float*)d_in[8];
    const float* Bm = (const float*)d_in[9];
    const float* u0 = (const float*)d_in[10];
    const float* s0 = (const float*)d_in[11];

    cudaFuncSetAttribute(ipm_kernel, cudaFuncAttributeMaxDynamicSharedMemorySize, SMEM_BYTES);

    setup_kernel<<<1, 128>>>(L, LP, LR, A, Bm, u0, s0);
    mlp_kernel<<<BATCH / 4, 128>>>(x, W1, b1, W2, b2);
    ipm_kernel<<<BATCH / WPB, NTH, SMEM_BYTES>>>((float*)d_out);
}

// round 5
// speedup vs baseline: 3.8531x; 1.0898x over previous
#include <cuda_runtime.h>
#include <math.h>

#define NIN   12
#define NOUT  4
#define NHID  512
#define NU    40
#define NB    108
#define NINEQ 148
#define BATCH 4096
#define IPM_ITERS 20
#define SIGMA 0.1f
#define BIGF  1000000000.0f
#define EPSF  0.0001f

#define WPB   8                 // warps per block
#define PPW   2                 // problems per warp
#define PPC   (WPB * PPW)       // 16 problems per CTA
#define NTH   (32 * WPB)

// shared layout (floats)
#define SQ_OFF 0                // 40*44 = 1760
#define SB_OFF 1760             // 108*44 = 4752
#define SH_OFF 6512             // 148
#define PR_OFF 6672             // 16B aligned

// per-problem layout (floats); H packed lower triangle (820)
#define P_H    0
#define P_D    824
#define P_V    972
#define P_U    1120             // 16B aligned
#define P_RHS  1160
#define P_DU   1200             // 16B aligned
#define P_LDI  1240
#define P_P    1280
#define PSTRIDE 1388

#define SMEM_FLOATS (PR_OFF + PPC * PSTRIDE)   // 28880
#define SMEM_BYTES  (SMEM_FLOATS * 4)          // 115520

__device__ float g_Q[NU * NU];
__device__ float g_B[NB * NU];
__device__ float g_h[NINEQ];
__device__ float g_p[BATCH * NU];

__device__ __forceinline__ float lrelu(float x) { return x > 0.f ? x : 0.01f * x; }
__device__ __forceinline__ int toff(int r) { return (r * (r + 1)) >> 1; }

// ================= setup =================
__global__ void setup_kernel(const float* __restrict__ L, const float* __restrict__ LP,
                             const float* __restrict__ LR, const float* __restrict__ A,
                             const float* __restrict__ Bm, const float* __restrict__ u0,
                             const float* __restrict__ s0) {
    __shared__ float sQx[144], sP[144], sR[16], sBp[9 * 48];
    __shared__ float sBh[NB * NU];
    __shared__ float sM[NB * NU];
    int tid = threadIdx.x;
    const int NTs = 128;

    for (int idx = tid; idx < 144; idx += NTs) {
        int i = idx / 12, j = idx % 12;
        int mn = i < j ? i : j;
        float a = 0.f, b = 0.f;
        for (int k = 0; k <= mn; k++) {
            a += L[i * 12 + k] * L[j * 12 + k];
            b += LP[i * 12 + k] * LP[j * 12 + k];
        }
        sQx[idx] = a + (i == j ? EPSF : 0.f);
        sP[idx]  = b + (i == j ? EPSF : 0.f);
    }
    for (int idx = tid; idx < 16; idx += NTs) {
        int i = idx / 4, j = idx % 4;
        int mn = i < j ? i : j;
        float a = 0.f;
        for (int k = 0; k <= mn; k++) a += LR[i * 4 + k] * LR[j * 4 + k];
        sR[idx] = a + (i == j ? EPSF : 0.f);
    }
    if (tid < 48) sBp[tid] = Bm[tid];
    __syncthreads();

    for (int m = 1; m < 9; m++) {
        if (tid < 48) {
            int i = tid / 4, o = tid % 4;
            float v = 0.f;
            for (int k = 0; k < 12; k++) v += A[i * 12 + k] * sBp[(m - 1) * 48 + k * 4 + o];
            sBp[m * 48 + tid] = v;
        }
        __syncthreads();
    }

    for (int idx = tid; idx < NB * NU; idx += NTs) {
        int row = idx / NU, col = idx % NU;
        int rb = row / 12, i = row % 12, cb = col / 4, o = col % 4;
        float v = (cb <= rb) ? sBp[(rb - cb) * 48 + i * 4 + o] : 0.f;
        sBh[idx] = v;
        g_B[idx] = v;
    }
    __syncthreads();

    for (int idx = tid; idx < NB * NU; idx += NTs) {
        int row = idx / NU, col = idx % NU;
        int rb = row / 12, i = row % 12;
        const float* Qd = (rb < 8) ? sQx : sP;
        float a = 0.f;
        for (int k = 0; k < 12; k++) a += Qd[i * 12 + k] * sBh[(rb * 12 + k) * NU + col];
        sM[idx] = a;
    }
    __syncthreads();

    for (int idx = tid; idx < NU * NU; idx += NTs) {
        int a_ = idx / NU, b_ = idx % NU;
        float v = (a_ / 4 == b_ / 4) ? sR[(a_ % 4) * 4 + (b_ % 4)] : 0.f;
        for (int r = 0; r < NB; r++) v += sBh[r * NU + a_] * sM[r * NU + b_];
        g_Q[idx] = v;
    }

    for (int j = tid; j < NINEQ; j += NTs) {
        float v = s0[j];
        if (j < NU) v += u0[j];
        else {
            for (int i = 0; i < NU; i++) v += sBh[(j - NU) * NU + i] * u0[i];
        }
        g_h[j] = v;
    }
}

// ================= MLP =================
__global__ void mlp_kernel(const float* __restrict__ x, const float* __restrict__ W1,
                           const float* __restrict__ b1, const float* __restrict__ W2,
                           const float* __restrict__ b2) {
    __shared__ float hbuf[4][NHID];
    int warp = threadIdx.x >> 5, lane = threadIdx.x & 31;
    int row = blockIdx.x * 4 + warp;

    float xr[NIN];
#pragma unroll
    for (int c = 0; c < NIN; c++) xr[c] = x[row * NIN + c];

#pragma unroll
    for (int t = 0; t < NHID / 32; t++) {
        int j = lane + 32 * t;
        const float* w = W1 + j * NIN;
        float acc = b1[j];
#pragma unroll
        for (int c = 0; c < NIN; c++) acc += w[c] * xr[c];
        hbuf[warp][j] = lrelu(acc);
    }
    __syncwarp();

    for (int k = 0; k < NU; k++) {
        const float* w = W2 + k * NHID;
        float acc = 0.f;
#pragma unroll
        for (int t = 0; t < NHID / 32; t++) {
            int j = lane + 32 * t;
            acc += w[j] * hbuf[warp][j];
        }
#pragma unroll
        for (int o = 16; o; o >>= 1) acc += __shfl_xor_sync(0xffffffffu, acc, o);
        if (lane == 0) g_p[row * NU + k] = lrelu(acc + b2[k]);
    }
}

// ================= IPM: two problems per warp =================
__global__ void __launch_bounds__(NTH, 2) ipm_kernel(float* __restrict__ out) {
    extern __shared__ float sm[];
    float* sQ  = sm + SQ_OFF;    // stride 44
    float* sB  = sm + SB_OFF;    // stride 44
    float* sh_ = sm + SH_OFF;

    int tid = threadIdx.x;
    int lane = tid & 31, wid = tid >> 5;

    for (int idx = tid; idx < NU * NU; idx += NTH) sQ[(idx / NU) * 44 + idx % NU] = g_Q[idx];
    for (int idx = tid; idx < NB * NU; idx += NTH) sB[(idx / NU) * 44 + idx % NU] = g_B[idx];
    for (int idx = tid; idx < NINEQ; idx += NTH) sh_[idx] = g_h[idx];
    __syncthreads();

    int pb = blockIdx.x * PPC + wid * PPW;     // global problem id of slot 0
    float* P0 = sm + PR_OFF + (wid * PPW) * PSTRIDE;
    float* P1 = P0 + PSTRIDE;

    if (lane < 32) {
        P0[P_U + lane] = 0.f;  P1[P_U + lane] = 0.f;
        P0[P_P + lane] = g_p[pb * NU + lane];
        P1[P_P + lane] = g_p[(pb + 1) * NU + lane];
    }
    if (lane < 8) {
        P0[P_U + 32 + lane] = 0.f;  P1[P_U + 32 + lane] = 0.f;
        P0[P_P + 32 + lane] = g_p[pb * NU + 32 + lane];
        P1[P_P + 32 + lane] = g_p[(pb + 1) * NU + 32 + lane];
    }

    // register state (aliased: rp -> ds, rv -> dlam after S4)
    float rs0[5], rs1[5], rl0[5], rl1[5], rp0[5], rp1[5], rv0[5], rv1[5];
#pragma unroll
    for (int t = 0; t < 5; t++) { rs0[t] = rs1[t] = rl0[t] = rl1[t] = 1.f; }
    float mu0 = 1.0f, mu1 = 1.0f;

    // H 4x4 block-pair assignment (25 pairs + 5 singles, lanes 30,31 idle)
    int bi = 0, bkA = 0, bkB = 0;
    bool hasB = false, active = false;
    {
        int idx = 0;
        for (int r = 0; r < 10; r++) {
            int np = (r + 1) / 2;
            for (int q = 0; q < np; q++) {
                if (idx == lane) { bi = r; bkA = 2 * q; bkB = 2 * q + 1; hasB = true; active = true; }
                idx++;
            }
        }
        for (int r = 0; r < 10; r += 2) {
            if (idx == lane) { bi = r; bkA = r; bkB = r; hasB = false; active = true; }
            idx++;
        }
    }
    bool diagA = (bkA == bi);      // singles
    bool diagB = (bkB == bi);      // odd-row last pair

    __syncwarp();

    for (int it = 0; it < IPM_ITERS; it++) {
        // ---- S0: d, rp, v (both problems, shared B-row loads) ----
#pragma unroll
        for (int t = 0; t < 5; t++) {
            int j = lane + 32 * t;
            if (j < NINEQ) {
                float A0, A1;
                if (j < NU) { A0 = P0[P_U + j]; A1 = P1[P_U + j]; }
                else {
                    const float4* br4 = (const float4*)(sB + (j - NU) * 44);
                    const float4* u40 = (const float4*)(P0 + P_U);
                    const float4* u41 = (const float4*)(P1 + P_U);
                    A0 = 0.f; A1 = 0.f;
#pragma unroll
                    for (int q = 0; q < 10; q++) {
                        float4 bv = br4[q];
                        float4 v0 = u40[q], v1 = u41[q];
                        A0 += bv.x * v0.x + bv.y * v0.y + bv.z * v0.z + bv.w * v0.w;
                        A1 += bv.x * v1.x + bv.y * v1.y + bv.z * v1.z + bv.w * v1.w;
                    }
                }
                float ri0 = 1.0f / rs0[t], ri1 = 1.0f / rs1[t];
                float d0 = rl0[t] * ri0, d1 = rl1[t] * ri1;
                P0[P_D + j] = d0;  P1[P_D + j] = d1;
                float hj = sh_[j];
                A0 += rs0[t] - hj;  A1 += rs1[t] - hj;
                float v0 = SIGMA * mu0 * ri0 + d0 * A0;
                float v1 = SIGMA * mu1 * ri1 + d1 * A1;
                rp0[t] = A0; rp1[t] = A1; rv0[t] = v0; rv1[t] = v1;
                P0[P_V + j] = v0;  P1[P_V + j] = v1;
            }
        }
        __syncwarp();

        // ---- S1: H (paired 4x4 blocks, packed lower-tri store), per problem ----
#pragma unroll
        for (int p = 0; p < 2; p++) {
            float* Pb = p ? P1 : P0;
            float* pH = Pb + P_H;
            float* pD = Pb + P_D;
            float acc0[4][4], acc1[4][4];
#pragma unroll
            for (int a = 0; a < 4; a++) {
                float4 v0 = *(const float4*)(sQ + (4 * bi + a) * 44 + 4 * bkA);
                acc0[a][0] = v0.x; acc0[a][1] = v0.y; acc0[a][2] = v0.z; acc0[a][3] = v0.w;
                float4 v1 = *(const float4*)(sQ + (4 * bi + a) * 44 + 4 * bkB);
                acc1[a][0] = v1.x; acc1[a][1] = v1.y; acc1[a][2] = v1.z; acc1[a][3] = v1.w;
            }
            if (diagA) {
#pragma unroll
                for (int a = 0; a < 4; a++) acc0[a][a] += pD[4 * bi + a];
            }
            if (diagB) {
#pragma unroll
                for (int a = 0; a < 4; a++) acc1[a][a] += pD[4 * bi + a];
            }
#pragma unroll 2
            for (int j = 0; j < NB; j++) {
                float dj = pD[NU + j];
                const float* br = sB + j * 44;
                float4 gav = *(const float4*)(br + 4 * bi);
                float4 g0  = *(const float4*)(br + 4 * bkA);
                float4 g1  = *(const float4*)(br + 4 * bkB);
                float sa[4];
                sa[0] = dj * gav.x; sa[1] = dj * gav.y; sa[2] = dj * gav.z; sa[3] = dj * gav.w;
                float gb0[4] = {g0.x, g0.y, g0.z, g0.w};
                float gb1[4] = {g1.x, g1.y, g1.z, g1.w};
#pragma unroll
                for (int a = 0; a < 4; a++)
#pragma unroll
                    for (int c = 0; c < 4; c++) {
                        acc0[a][c] += sa[a] * gb0[c];
                        acc1[a][c] += sa[a] * gb1[c];
                    }
            }
            if (active) {
#pragma unroll
                for (int a = 0; a < 4; a++) {
                    int row = 4 * bi + a;
                    int ob = toff(row);
#pragma unroll
                    for (int c = 0; c < 4; c++) {
                        if (!diagA || c <= a) pH[ob + 4 * bkA + c] = acc0[a][c];
                    }
                    if (hasB) {
#pragma unroll
                        for (int c = 0; c < 4; c++) {
                            if (!diagB || c <= a) pH[ob + 4 * bkB + c] = acc1[a][c];
                        }
                    }
                }
            }
        }

        // ---- rhs = -(Qu + p + v[:40] + B^T v[40:]), both problems share Q/B loads ----
        {
            float a0 = P0[P_P + lane] + P0[P_V + lane];
            float c0 = P1[P_P + lane] + P1[P_V + lane];
            float a1 = 0.f, c1 = 0.f;
            if (lane < 8) {
                a1 = P0[P_P + 32 + lane] + P0[P_V + 32 + lane];
                c1 = P1[P_P + 32 + lane] + P1[P_V + 32 + lane];
            }
            const float4* q0 = (const float4*)(sQ + lane * 44);
            const float4* q1 = (const float4*)(sQ + (32 + lane) * 44);
            const float4* u40 = (const float4*)(P0 + P_U);
            const float4* u41 = (const float4*)(P1 + P_U);
#pragma unroll
            for (int q = 0; q < 10; q++) {
                float4 qv0 = q0[q];
                float4 v0 = u40[q], v1 = u41[q];
                a0 += qv0.x * v0.x + qv0.y * v0.y + qv0.z * v0.z + qv0.w * v0.w;
                c0 += qv0.x * v1.x + qv0.y * v1.y + qv0.z * v1.z + qv0.w * v1.w;
                if (lane < 8) {
                    float4 qv1 = q1[q];
                    a1 += qv1.x * v0.x + qv1.y * v0.y + qv1.z * v0.z + qv1.w * v0.w;
                    c1 += qv1.x * v1.x + qv1.y * v1.y + qv1.z * v1.z + qv1.w * v1.w;
                }
            }
#pragma unroll 2
            for (int j = 0; j < NB; j++) {
                const float* br = sB + j * 44;
                float v0 = P0[P_V + NU + j], v1 = P1[P_V + NU + j];
                float bl = br[lane];
                a0 += v0 * bl;  c0 += v1 * bl;
                if (lane < 8) {
                    float bh = br[32 + lane];
                    a1 += v0 * bh;  c1 += v1 * bh;
                }
            }
            P0[P_RHS + lane] = -a0;  P1[P_RHS + lane] = -c0;
            if (lane < 8) { P0[P_RHS + 32 + lane] = -a1;  P1[P_RHS + 32 + lane] = -c1; }
        }
        __syncwarp();

        // ---- S3: blocked Cholesky (panel=8), both problems interleaved ----
        float* pH0 = P0 + P_H;
        float* pH1 = P1 + P_H;
        for (int pp = 0; pp < 5; pp++) {
            int k0 = 8 * pp;
            for (int kk = 0; kk < 8; kk++) {
                int k = k0 + kk;
                int ok = toff(k);
                float h0 = pH0[ok + k], h1 = pH1[ok + k];
                float i0 = rsqrtf(h0); i0 = i0 * (1.5f - 0.5f * h0 * i0 * i0);
                float i1 = rsqrtf(h1); i1 = i1 * (1.5f - 0.5f * h1 * i1 * i1);
                if (lane == 0) { P0[P_LDI + k] = i0; P1[P_LDI + k] = i1; }
                int r0 = k + 1 + lane, r1 = r0 + 32;
                int or0 = toff(r0), or1 = toff(r1);
                float vA0 = 0.f, vA1 = 0.f, vB0 = 0.f, vB1 = 0.f;
                if (r0 < NU) {
                    vA0 = pH0[or0 + k] * i0;  pH0[or0 + k] = vA0;
                    vB0 = pH1[or0 + k] * i1;  pH1[or0 + k] = vB0;
                }
                if (r1 < NU) {
                    vA1 = pH0[or1 + k] * i0;  pH0[or1 + k] = vA1;
                    vB1 = pH1[or1 + k] * i1;  pH1[or1 + k] = vB1;
                }
                __syncwarp();
                for (int j = k + 1; j < k0 + 8; j++) {
                    float mA = __shfl_sync(0xffffffffu, vA0, j - k - 1);
                    float mB = __shfl_sync(0xffffffffu, vB0, j - k - 1);
                    if (r0 < NU && r0 >= j) { pH0[or0 + j] -= vA0 * mA;  pH1[or0 + j] -= vB0 * mB; }
                    if (r1 < NU)            { pH0[or1 + j] -= vA1 * mA;  pH1[or1 + j] -= vB1 * mB; }
                }
                __syncwarp();
            }
            if (pp < 4) {
                int base = k0 + 8;
                int nbk = (NU - base) >> 2;
                int cnt = nbk * (nbk + 1) / 2;
                for (int bb = lane; bb < cnt; bb += 32) {
                    int t = bb, r = 0;
                    while (t > r) { t -= r + 1; r++; }
                    int c = t;
                    int ri = base + 4 * r, ci = base + 4 * c;
                    bool diag = (r == c);
                    int oR[4], oC[4];
                    oR[0] = toff(ri);
                    oR[1] = oR[0] + ri + 1; oR[2] = oR[1] + ri + 2; oR[3] = oR[2] + ri + 3;
                    oC[0] = toff(ci);
                    oC[1] = oC[0] + ci + 1; oC[2] = oC[1] + ci + 2; oC[3] = oC[2] + ci + 3;
#pragma unroll
                    for (int p = 0; p < 2; p++) {
                        float* pH = p ? pH1 : pH0;
                        float a2[4][4];
#pragma unroll
                        for (int a = 0; a < 4; a++)
#pragma unroll
                            for (int cb = 0; cb < 4; cb++)
                                a2[a][cb] = pH[oR[a] + ci + cb];
#pragma unroll
                        for (int kk = 0; kk < 8; kk++) {
                            float la[4], lb[4];
#pragma unroll
                            for (int a = 0; a < 4; a++) la[a] = pH[oR[a] + k0 + kk];
#pragma unroll
                            for (int cb = 0; cb < 4; cb++) lb[cb] = pH[oC[cb] + k0 + kk];
#pragma unroll
                            for (int a = 0; a < 4; a++)
#pragma unroll
                                for (int cb = 0; cb < 4; cb++)
                                    a2[a][cb] -= la[a] * lb[cb];
                        }
#pragma unroll
                        for (int a = 0; a < 4; a++)
#pragma unroll
                            for (int cb = 0; cb < 4; cb++)
                                if (!diag || cb <= a) pH[oR[a] + ci + cb] = a2[a][cb];
                    }
                }
                __syncwarp();
            }
        }

        // ---- triangular solves, both problems interleaved ----
        {
            int offL0 = toff(lane);
            int offL1 = toff(32 + lane);
            float a0 = P0[P_RHS + lane];
            float c0 = P1[P_RHS + lane];
            float a1 = (lane < 8) ? P0[P_RHS + 32 + lane] : 0.f;
            float c1 = (lane < 8) ? P1[P_RHS + 32 + lane] : 0.f;
            for (int k = 0; k < NU; k++) {
                float sA = (k < 32) ? a0 : a1;
                float sC = (k < 32) ? c0 : c1;
                float yA = __shfl_sync(0xffffffffu, sA, k & 31) * P0[P_LDI + k];
                float yC = __shfl_sync(0xffffffffu, sC, k & 31) * P1[P_LDI + k];
                if (k < 32) { if (lane == k) { a0 = yA; c0 = yC; } }
                else        { if (lane == k - 32) { a1 = yA; c1 = yC; } }
                if (lane > k) { a0 -= pH0[offL0 + k] * yA;  c0 -= pH1[offL0 + k] * yC; }
                if (lane < 8 && 32 + lane > k) { a1 -= pH0[offL1 + k] * yA;  c1 -= pH1[offL1 + k] * yC; }
            }
            int offk = toff(NU - 1);
            for (int k = NU - 1; k >= 0; k--) {
                float sA = (k < 32) ? a0 : a1;
                float sC = (k < 32) ? c0 : c1;
                float xA = __shfl_sync(0xffffffffu, sA, k & 31) * P0[P_LDI + k];
                float xC = __shfl_sync(0xffffffffu, sC, k & 31) * P1[P_LDI + k];
                if (k < 32) { if (lane == k) { a0 = xA; c0 = xC; } }
                else        { if (lane == k - 32) { a1 = xA; c1 = xC; } }
                if (lane < k) { a0 -= pH0[offk + lane] * xA;  c0 -= pH1[offk + lane] * xC; }
                if (lane < 8 && 32 + lane < k) { a1 -= pH0[offk + 32 + lane] * xA;  c1 -= pH1[offk + 32 + lane] * xC; }
                offk -= k;
            }
            P0[P_DU + lane] = a0;  P1[P_DU + lane] = c0;
            if (lane < 8) { P0[P_DU + 32 + lane] = a1;  P1[P_DU + 32 + lane] = c1; }
        }
        __syncwarp();

        // ---- S4: ds, dlam, alpha (shared B-row loads) ----
        float am0 = BIGF, am1 = BIGF;
#pragma unroll
        for (int t = 0; t < 5; t++) {
            int j = lane + 32 * t;
            if (j < NINEQ) {
                float g0, g1;
                if (j < NU) { g0 = P0[P_DU + j]; g1 = P1[P_DU + j]; }
                else {
                    const float4* br4 = (const float4*)(sB + (j - NU) * 44);
                    const float4* d40 = (const float4*)(P0 + P_DU);
                    const float4* d41 = (const float4*)(P1 + P_DU);
                    g0 = 0.f; g1 = 0.f;
#pragma unroll
                    for (int q = 0; q < 10; q++) {
                        float4 bv = br4[q];
                        float4 v0 = d40[q], v1 = d41[q];
                        g0 += bv.x * v0.x + bv.y * v0.y + bv.z * v0.z + bv.w * v0.w;
                        g1 += bv.x * v1.x + bv.y * v1.y + bv.z * v1.z + bv.w * v1.w;
                    }
                }
                float d0 = P0[P_D + j], d1 = P1[P_D + j];
                float ds0 = -rp0[t] - g0, ds1 = -rp1[t] - g1;
                float dl0 = rv0[t] - rl0[t] + d0 * g0;
                float dl1 = rv1[t] - rl1[t] + d1 * g1;
                rp0[t] = ds0; rp1[t] = ds1; rv0[t] = dl0; rv1[t] = dl1;
                float q0 = (ds0 < 0.f) ? -rs0[t] / ds0 : BIGF;
                float q1 = (dl0 < 0.f) ? -rl0[t] / dl0 : BIGF;
                am0 = fminf(am0, fminf(q0, q1));
                float q2 = (ds1 < 0.f) ? -rs1[t] / ds1 : BIGF;
                float q3 = (dl1 < 0.f) ? -rl1[t] / dl1 : BIGF;
                am1 = fminf(am1, fminf(q2, q3));
            }
        }
#pragma unroll
        for (int o = 16; o; o >>= 1) {
            am0 = fminf(am0, __shfl_xor_sync(0xffffffffu, am0, o));
            am1 = fminf(am1, __shfl_xor_sync(0xffffffffu, am1, o));
        }
        float al0 = fminf(1.0f, 0.99f * am0);
        float al1 = fminf(1.0f, 0.99f * am1);

        // ---- S5: update + mu ----
        float ls0 = 0.f, ls1 = 0.f;
#pragma unroll
        for (int t = 0; t < 5; t++) {
            int j = lane + 32 * t;
            if (j < NINEQ) {
                rs0[t] += al0 * rp0[t];  rl0[t] += al0 * rv0[t];  ls0 += rs0[t] * rl0[t];
                rs1[t] += al1 * rp1[t];  rl1[t] += al1 * rv1[t];  ls1 += rs1[t] * rl1[t];
            }
        }
#pragma unroll
        for (int o = 16; o; o >>= 1) {
            ls0 += __shfl_xor_sync(0xffffffffu, ls0, o);
            ls1 += __shfl_xor_sync(0xffffffffu, ls1, o);
        }
        mu0 = ls0 * (1.0f / 148.0f);
        mu1 = ls1 * (1.0f / 148.0f);

        P0[P_U + lane] += al0 * P0[P_DU + lane];
        P1[P_U + lane] += al1 * P1[P_DU + lane];
        if (lane < 8) {
            P0[P_U + 32 + lane] += al0 * P0[P_DU + 32 + lane];
            P1[P_U + 32 + lane] += al1 * P1[P_DU + 32 + lane];
        }
        __syncwarp();
    }

    // ---- output ----
#pragma unroll
    for (int p = 0; p < 2; p++) {
        float* Pb = p ? P1 : P0;
        const float4* q0 = (const float4*)(sQ + lane * 44);
        const float4* q1 = (const float4*)(sQ + (32 + lane) * 44);
        const float4* u4 = (const float4*)(Pb + P_U);
        float qu0 = 0.f, qu1 = 0.f;
#pragma unroll
        for (int q = 0; q < 10; q++) {
            float4 uv = u4[q];
            float4 qv0 = q0[q];
            qu0 += qv0.x * uv.x + qv0.y * uv.y + qv0.z * uv.z + qv0.w * uv.w;
            if (lane < 8) {
                float4 qv1 = q1[q];
                qu1 += qv1.x * uv.x + qv1.y * uv.y + qv1.z * uv.z + qv1.w * uv.w;
            }
        }
        float part = Pb[P_U + lane] * (0.5f * qu0 + Pb[P_P + lane]);
        if (lane < 8) part += Pb[P_U + 32 + lane] * (0.5f * qu1 + Pb[P_P + 32 + lane]);
#pragma unroll
        for (int o = 16; o; o >>= 1) part += __shfl_xor_sync(0xffffffffu, part, o);
        if (lane == 0) {
            out[pb + p] = part;
            out[BATCH + pb + p] = Pb[P_U + 0];
        }
    }
}

// ================= launch =================
extern "C" void kernel_launch(void* const* d_in, const int* in_sizes, int n_in,
                              void* d_out, int out_size) {
    const float* x  = (const float*)d_in[0];
    const float* W1 = (const float*)d_in[1];
    const float* b1 = (const float*)d_in[2];
    const float* W2 = (const float*)d_in[3];
    const float* b2 = (const float*)d_in[4];
    const float* L  = (const float*)d_in[5];
    const float* LP = (const float*)d_in[6];
    const float* LR = (const float*)d_in[7];
    const float* A  = (const float*)d_in[8];
    const float* Bm = (const float*)d_in[9];
    const float* u0 = (const float*)d_in[10];
    const float* s0 = (const float*)d_in[11];

    cudaFuncSetAttribute(ipm_kernel, cudaFuncAttributeMaxDynamicSharedMemorySize, SMEM_BYTES);

    setup_kernel<<<1, 128>>>(L, LP, LR, A, Bm, u0, s0);
    mlp_kernel<<<BATCH / 4, 128>>>(x, W1, b1, W2, b2);
    ipm_kernel<<<BATCH / PPC, NTH, SMEM_BYTES>>>((float*)d_out);
}

// round 6
// speedup vs baseline: 4.6326x; 1.2023x over previous
#include <cuda_runtime.h>
#include <math.h>

#define NIN   12
#define NOUT  4
#define NHID  512
#define NU    40
#define NB    108
#define NINEQ 148
#define BATCH 4096
#define IPM_ITERS 20
#define SIGMA 0.1f
#define BIGF  1000000000.0f
#define EPSF  0.0001f

#define WPB   8                 // warps per block
#define PPW   2                 // problems per warp (packed f32x2)
#define PPC   (WPB * PPW)
#define NTH   (32 * WPB)

// shared scalar layout (floats)
#define SQ_OFF 0                // 40*44 = 1760
#define SB_OFF 1760             // 108*44 = 4752
#define SH_OFF 6512             // 148 -> 6660, pad to 6672
#define PR_OFF 6672

// per-pair packed layout (u64 units; element i of both problems in one u64)
#define H2_OFF   0              // 820 (packed lower triangle)
#define D2_OFF   820            // 148
#define V2_OFF   968            // 148
#define U2_OFF   1116           // 40
#define RHS2_OFF 1156           // 40
#define DU2_OFF  1196           // 40
#define LDI2_OFF 1236           // 40
#define P2_OFF   1276           // 40  -> 1316
#define PSTRIDE_U64 1320

#define SMEM_FLOATS (PR_OFF + WPB * PSTRIDE_U64 * 2)   // 6672 + 21120 = 27792
#define SMEM_BYTES  (SMEM_FLOATS * 4)                  // 111168

typedef unsigned long long u64;

__device__ __forceinline__ u64 pk2(float lo, float hi) {
    u64 r; asm("mov.b64 %0,{%1,%2};" : "=l"(r) : "f"(lo), "f"(hi)); return r;
}
__device__ __forceinline__ void upk2(u64 v, float& lo, float& hi) {
    asm("mov.b64 {%0,%1},%2;" : "=f"(lo), "=f"(hi) : "l"(v));
}
__device__ __forceinline__ u64 rep2(float x) { return pk2(x, x); }
__device__ __forceinline__ u64 fma2(u64 a, u64 b, u64 c) {
    u64 d; asm("fma.rn.f32x2 %0,%1,%2,%3;" : "=l"(d) : "l"(a), "l"(b), "l"(c)); return d;
}
__device__ __forceinline__ u64 mul2(u64 a, u64 b) {
    u64 d; asm("mul.rn.f32x2 %0,%1,%2;" : "=l"(d) : "l"(a), "l"(b)); return d;
}
__device__ __forceinline__ u64 add2(u64 a, u64 b) {
    u64 d; asm("add.rn.f32x2 %0,%1,%2;" : "=l"(d) : "l"(a), "l"(b)); return d;
}
__device__ __forceinline__ u64 neg2(u64 a) { return a ^ 0x8000000080000000ULL; }

__device__ float g_Q[NU * NU];
__device__ float g_B[NB * NU];
__device__ float g_h[NINEQ];
__device__ float g_p[BATCH * NU];

__device__ __forceinline__ float lrelu(float x) { return x > 0.f ? x : 0.01f * x; }
__device__ __forceinline__ int toff(int r) { return (r * (r + 1)) >> 1; }

// ================= setup =================
__global__ void setup_kernel(const float* __restrict__ L, const float* __restrict__ LP,
                             const float* __restrict__ LR, const float* __restrict__ A,
                             const float* __restrict__ Bm, const float* __restrict__ u0,
                             const float* __restrict__ s0) {
    __shared__ float sQx[144], sP[144], sR[16], sBp[9 * 48];
    __shared__ float sBh[NB * NU];
    __shared__ float sM[NB * NU];
    int tid = threadIdx.x;
    const int NTs = 128;

    for (int idx = tid; idx < 144; idx += NTs) {
        int i = idx / 12, j = idx % 12;
        int mn = i < j ? i : j;
        float a = 0.f, b = 0.f;
        for (int k = 0; k <= mn; k++) {
            a += L[i * 12 + k] * L[j * 12 + k];
            b += LP[i * 12 + k] * LP[j * 12 + k];
        }
        sQx[idx] = a + (i == j ? EPSF : 0.f);
        sP[idx]  = b + (i == j ? EPSF : 0.f);
    }
    for (int idx = tid; idx < 16; idx += NTs) {
        int i = idx / 4, j = idx % 4;
        int mn = i < j ? i : j;
        float a = 0.f;
        for (int k = 0; k <= mn; k++) a += LR[i * 4 + k] * LR[j * 4 + k];
        sR[idx] = a + (i == j ? EPSF : 0.f);
    }
    if (tid < 48) sBp[tid] = Bm[tid];
    __syncthreads();

    for (int m = 1; m < 9; m++) {
        if (tid < 48) {
            int i = tid / 4, o = tid % 4;
            float v = 0.f;
            for (int k = 0; k < 12; k++) v += A[i * 12 + k] * sBp[(m - 1) * 48 + k * 4 + o];
            sBp[m * 48 + tid] = v;
        }
        __syncthreads();
    }

    for (int idx = tid; idx < NB * NU; idx += NTs) {
        int row = idx / NU, col = idx % NU;
        int rb = row / 12, i = row % 12, cb = col / 4, o = col % 4;
        float v = (cb <= rb) ? sBp[(rb - cb) * 48 + i * 4 + o] : 0.f;
        sBh[idx] = v;
        g_B[idx] = v;
    }
    __syncthreads();

    for (int idx = tid; idx < NB * NU; idx += NTs) {
        int row = idx / NU, col = idx % NU;
        int rb = row / 12, i = row % 12;
        const float* Qd = (rb < 8) ? sQx : sP;
        float a = 0.f;
        for (int k = 0; k < 12; k++) a += Qd[i * 12 + k] * sBh[(rb * 12 + k) * NU + col];
        sM[idx] = a;
    }
    __syncthreads();

    for (int idx = tid; idx < NU * NU; idx += NTs) {
        int a_ = idx / NU, b_ = idx % NU;
        float v = (a_ / 4 == b_ / 4) ? sR[(a_ % 4) * 4 + (b_ % 4)] : 0.f;
        for (int r = 0; r < NB; r++) v += sBh[r * NU + a_] * sM[r * NU + b_];
        g_Q[idx] = v;
    }

    for (int j = tid; j < NINEQ; j += NTs) {
        float v = s0[j];
        if (j < NU) v += u0[j];
        else {
            for (int i = 0; i < NU; i++) v += sBh[(j - NU) * NU + i] * u0[i];
        }
        g_h[j] = v;
    }
}

// ================= MLP =================
__global__ void mlp_kernel(const float* __restrict__ x, const float* __restrict__ W1,
                           const float* __restrict__ b1, const float* __restrict__ W2,
                           const float* __restrict__ b2) {
    __shared__ float hbuf[4][NHID];
    int warp = threadIdx.x >> 5, lane = threadIdx.x & 31;
    int row = blockIdx.x * 4 + warp;

    float xr[NIN];
#pragma unroll
    for (int c = 0; c < NIN; c++) xr[c] = x[row * NIN + c];

#pragma unroll
    for (int t = 0; t < NHID / 32; t++) {
        int j = lane + 32 * t;
        const float* w = W1 + j * NIN;
        float acc = b1[j];
#pragma unroll
        for (int c = 0; c < NIN; c++) acc += w[c] * xr[c];
        hbuf[warp][j] = lrelu(acc);
    }
    __syncwarp();

    for (int k = 0; k < NU; k++) {
        const float* w = W2 + k * NHID;
        float acc = 0.f;
#pragma unroll
        for (int t = 0; t < NHID / 32; t++) {
            int j = lane + 32 * t;
            acc += w[j] * hbuf[warp][j];
        }
#pragma unroll
        for (int o = 16; o; o >>= 1) acc += __shfl_xor_sync(0xffffffffu, acc, o);
        if (lane == 0) g_p[row * NU + k] = lrelu(acc + b2[k]);
    }
}

// ================= IPM: two problems per warp, f32x2-packed =================
__global__ void __launch_bounds__(NTH, 2) ipm_kernel(float* __restrict__ out) {
    extern __shared__ float sm[];
    float* sQ  = sm + SQ_OFF;    // stride 44
    float* sB  = sm + SB_OFF;    // stride 44
    float* sh_ = sm + SH_OFF;

    int tid = threadIdx.x;
    int lane = tid & 31, wid = tid >> 5;

    for (int idx = tid; idx < NU * NU; idx += NTH) sQ[(idx / NU) * 44 + idx % NU] = g_Q[idx];
    for (int idx = tid; idx < NB * NU; idx += NTH) sB[(idx / NU) * 44 + idx % NU] = g_B[idx];
    for (int idx = tid; idx < NINEQ; idx += NTH) sh_[idx] = g_h[idx];
    __syncthreads();

    int pb = blockIdx.x * PPC + wid * PPW;
    u64* PR = (u64*)(sm + PR_OFF) + wid * PSTRIDE_U64;
    u64* pH2  = PR + H2_OFF;
    u64* pD2  = PR + D2_OFF;
    u64* pV2  = PR + V2_OFF;
    u64* pU2  = PR + U2_OFF;
    u64* pR2  = PR + RHS2_OFF;
    u64* pDU2 = PR + DU2_OFF;
    u64* pLi2 = PR + LDI2_OFF;
    u64* pP2  = PR + P2_OFF;

    if (lane < NU) {
        pU2[lane] = 0ULL;
        pP2[lane] = pk2(g_p[pb * NU + lane], g_p[(pb + 1) * NU + lane]);
    }
    if (lane < 8) {
        pU2[32 + lane] = 0ULL;
        pP2[32 + lane] = pk2(g_p[pb * NU + 32 + lane], g_p[(pb + 1) * NU + 32 + lane]);
    }

    // scalar per-lane state
    float rs0[5], rs1[5], rl0[5], rl1[5], rp0[5], rp1[5];
#pragma unroll
    for (int t = 0; t < 5; t++) { rs0[t] = rs1[t] = rl0[t] = rl1[t] = 1.f; }
    float mu0 = 1.0f, mu1 = 1.0f;

    // H 4x4 block-pair assignment (25 pairs + 5 singles, lanes 30,31 idle)
    int bi = 0, bkA = 0, bkB = 0;
    bool hasB = false, active = false;
    {
        int idx = 0;
        for (int r = 0; r < 10; r++) {
            int np = (r + 1) / 2;
            for (int q = 0; q < np; q++) {
                if (idx == lane) { bi = r; bkA = 2 * q; bkB = 2 * q + 1; hasB = true; active = true; }
                idx++;
            }
        }
        for (int r = 0; r < 10; r += 2) {
            if (idx == lane) { bi = r; bkA = r; bkB = r; hasB = false; active = true; }
            idx++;
        }
    }
    bool diagA = (bkA == bi);
    bool diagB = (bkB == bi);

    __syncwarp();

    for (int it = 0; it < IPM_ITERS; it++) {
        // ---- S0: d, rp, v ----
#pragma unroll
        for (int t = 0; t < 5; t++) {
            int j = lane + 32 * t;
            if (j < NINEQ) {
                float A0, A1;
                if (j < NU) upk2(pU2[j], A0, A1);
                else {
                    const float4* br4 = (const float4*)(sB + (j - NU) * 44);
                    u64 acc = 0ULL;
#pragma unroll
                    for (int q = 0; q < 10; q++) {
                        float4 bv = br4[q];
                        acc = fma2(rep2(bv.x), pU2[4 * q + 0], acc);
                        acc = fma2(rep2(bv.y), pU2[4 * q + 1], acc);
                        acc = fma2(rep2(bv.z), pU2[4 * q + 2], acc);
                        acc = fma2(rep2(bv.w), pU2[4 * q + 3], acc);
                    }
                    upk2(acc, A0, A1);
                }
                float ri0 = 1.0f / rs0[t], ri1 = 1.0f / rs1[t];
                float d0 = rl0[t] * ri0, d1 = rl1[t] * ri1;
                pD2[j] = pk2(d0, d1);
                float hj = sh_[j];
                A0 += rs0[t] - hj;  A1 += rs1[t] - hj;
                rp0[t] = A0;  rp1[t] = A1;
                float v0 = SIGMA * mu0 * ri0 + d0 * A0;
                float v1 = SIGMA * mu1 * ri1 + d1 * A1;
                pV2[j] = pk2(v0, v1);
            }
        }
        __syncwarp();

        // ---- S1: H = Q + diag(d) + B^T diag(d) B  (packed, paired blocks) ----
        {
            u64 acc0[4][4], acc1[4][4];
#pragma unroll
            for (int a = 0; a < 4; a++) {
                float4 v0 = *(const float4*)(sQ + (4 * bi + a) * 44 + 4 * bkA);
                acc0[a][0] = rep2(v0.x); acc0[a][1] = rep2(v0.y);
                acc0[a][2] = rep2(v0.z); acc0[a][3] = rep2(v0.w);
                float4 v1 = *(const float4*)(sQ + (4 * bi + a) * 44 + 4 * bkB);
                acc1[a][0] = rep2(v1.x); acc1[a][1] = rep2(v1.y);
                acc1[a][2] = rep2(v1.z); acc1[a][3] = rep2(v1.w);
            }
            if (diagA) {
#pragma unroll
                for (int a = 0; a < 4; a++) acc0[a][a] = add2(acc0[a][a], pD2[4 * bi + a]);
            }
            if (diagB) {
#pragma unroll
                for (int a = 0; a < 4; a++) acc1[a][a] = add2(acc1[a][a], pD2[4 * bi + a]);
            }
#pragma unroll 2
            for (int j = 0; j < NB; j++) {
                u64 dp = pD2[NU + j];
                const float* br = sB + j * 44;
                float4 gav = *(const float4*)(br + 4 * bi);
                float4 g0  = *(const float4*)(br + 4 * bkA);
                float4 g1  = *(const float4*)(br + 4 * bkB);
                u64 sa[4];
                sa[0] = mul2(dp, rep2(gav.x)); sa[1] = mul2(dp, rep2(gav.y));
                sa[2] = mul2(dp, rep2(gav.z)); sa[3] = mul2(dp, rep2(gav.w));
                u64 rb0[4] = {rep2(g0.x), rep2(g0.y), rep2(g0.z), rep2(g0.w)};
                u64 rb1[4] = {rep2(g1.x), rep2(g1.y), rep2(g1.z), rep2(g1.w)};
#pragma unroll
                for (int a = 0; a < 4; a++)
#pragma unroll
                    for (int c = 0; c < 4; c++) {
                        acc0[a][c] = fma2(sa[a], rb0[c], acc0[a][c]);
                        acc1[a][c] = fma2(sa[a], rb1[c], acc1[a][c]);
                    }
            }
            if (active) {
#pragma unroll
                for (int a = 0; a < 4; a++) {
                    int ob = toff(4 * bi + a);
#pragma unroll
                    for (int c = 0; c < 4; c++)
                        if (!diagA || c <= a) pH2[ob + 4 * bkA + c] = acc0[a][c];
                    if (hasB) {
#pragma unroll
                        for (int c = 0; c < 4; c++)
                            if (!diagB || c <= a) pH2[ob + 4 * bkB + c] = acc1[a][c];
                    }
                }
            }
        }

        // ---- rhs = -(Qu + p + v[:40] + B^T v[40:]) (packed) ----
        {
            u64 A0 = add2(pP2[lane], pV2[lane]);
            u64 A1 = (lane < 8) ? add2(pP2[32 + lane], pV2[32 + lane]) : 0ULL;
            const float4* q0 = (const float4*)(sQ + lane * 44);
            const float4* q1 = (const float4*)(sQ + (32 + lane) * 44);
#pragma unroll
            for (int q = 0; q < 10; q++) {
                float4 qv0 = q0[q];
                A0 = fma2(rep2(qv0.x), pU2[4 * q + 0], A0);
                A0 = fma2(rep2(qv0.y), pU2[4 * q + 1], A0);
                A0 = fma2(rep2(qv0.z), pU2[4 * q + 2], A0);
                A0 = fma2(rep2(qv0.w), pU2[4 * q + 3], A0);
                if (lane < 8) {
                    float4 qv1 = q1[q];
                    A1 = fma2(rep2(qv1.x), pU2[4 * q + 0], A1);
                    A1 = fma2(rep2(qv1.y), pU2[4 * q + 1], A1);
                    A1 = fma2(rep2(qv1.z), pU2[4 * q + 2], A1);
                    A1 = fma2(rep2(qv1.w), pU2[4 * q + 3], A1);
                }
            }
#pragma unroll 2
            for (int j = 0; j < NB; j++) {
                const float* br = sB + j * 44;
                u64 vj = pV2[NU + j];
                A0 = fma2(rep2(br[lane]), vj, A0);
                if (lane < 8) A1 = fma2(rep2(br[32 + lane]), vj, A1);
            }
            pR2[lane] = neg2(A0);
            if (lane < 8) pR2[32 + lane] = neg2(A1);
        }
        __syncwarp();

        // ---- S3: blocked Cholesky (panel=8), packed ----
        for (int pp = 0; pp < 5; pp++) {
            int k0 = 8 * pp;
            for (int kk = 0; kk < 8; kk++) {
                int k = k0 + kk;
                int ok = toff(k);
                float h0, h1;
                upk2(pH2[ok + k], h0, h1);
                float i0 = rsqrtf(h0); i0 = i0 * (1.5f - 0.5f * h0 * i0 * i0);
                float i1 = rsqrtf(h1); i1 = i1 * (1.5f - 0.5f * h1 * i1 * i1);
                u64 ip = pk2(i0, i1);
                if (lane == 0) pLi2[k] = ip;
                int r0 = k + 1 + lane, r1 = r0 + 32;
                int or0 = toff(r0), or1 = toff(r1);
                u64 v0 = 0ULL, v1 = 0ULL;
                if (r0 < NU) { v0 = mul2(pH2[or0 + k], ip); pH2[or0 + k] = v0; }
                if (r1 < NU) { v1 = mul2(pH2[or1 + k], ip); pH2[or1 + k] = v1; }
                __syncwarp();
                for (int j = k + 1; j < k0 + 8; j++) {
                    u64 m = __shfl_sync(0xffffffffu, v0, j - k - 1);
                    u64 nm = neg2(m);
                    if (r0 < NU && r0 >= j) pH2[or0 + j] = fma2(nm, v0, pH2[or0 + j]);
                    if (r1 < NU)            pH2[or1 + j] = fma2(nm, v1, pH2[or1 + j]);
                }
                __syncwarp();
            }
            if (pp < 4) {
                int base = k0 + 8;
                int nbk = (NU - base) >> 2;
                int cnt = nbk * (nbk + 1) / 2;
                for (int bb = lane; bb < cnt; bb += 32) {
                    int t = bb, r = 0;
                    while (t > r) { t -= r + 1; r++; }
                    int c = t;
                    int ri = base + 4 * r, ci = base + 4 * c;
                    bool diag = (r == c);
                    int oR[4], oC[4];
                    oR[0] = toff(ri);
                    oR[1] = oR[0] + ri + 1; oR[2] = oR[1] + ri + 2; oR[3] = oR[2] + ri + 3;
                    oC[0] = toff(ci);
                    oC[1] = oC[0] + ci + 1; oC[2] = oC[1] + ci + 2; oC[3] = oC[2] + ci + 3;
                    u64 a2[4][4];
#pragma unroll
                    for (int a = 0; a < 4; a++)
#pragma unroll
                        for (int cb = 0; cb < 4; cb++)
                            a2[a][cb] = pH2[oR[a] + ci + cb];
#pragma unroll
                    for (int kk = 0; kk < 8; kk++) {
                        u64 nla[4], lb[4];
#pragma unroll
                        for (int a = 0; a < 4; a++) nla[a] = neg2(pH2[oR[a] + k0 + kk]);
#pragma unroll
                        for (int cb = 0; cb < 4; cb++) lb[cb] = pH2[oC[cb] + k0 + kk];
#pragma unroll
                        for (int a = 0; a < 4; a++)
#pragma unroll
                            for (int cb = 0; cb < 4; cb++)
                                a2[a][cb] = fma2(nla[a], lb[cb], a2[a][cb]);
                    }
#pragma unroll
                    for (int a = 0; a < 4; a++)
#pragma unroll
                        for (int cb = 0; cb < 4; cb++)
                            if (!diag || cb <= a) pH2[oR[a] + ci + cb] = a2[a][cb];
                }
                __syncwarp();
            }
        }

        // ---- triangular solves (packed) ----
        {
            int offL0 = toff(lane);
            int offL1 = toff(32 + lane);
            u64 a0 = pR2[lane];
            u64 a1 = (lane < 8) ? pR2[32 + lane] : 0ULL;
            for (int k = 0; k < NU; k++) {
                u64 src = (k < 32) ? a0 : a1;
                u64 y = mul2(__shfl_sync(0xffffffffu, src, k & 31), pLi2[k]);
                if (k < 32) { if (lane == k) a0 = y; }
                else        { if (lane == k - 32) a1 = y; }
                u64 ny = neg2(y);
                if (lane > k) a0 = fma2(pH2[offL0 + k], ny, a0);
                if (lane < 8 && 32 + lane > k) a1 = fma2(pH2[offL1 + k], ny, a1);
            }
            int offk = toff(NU - 1);
            for (int k = NU - 1; k >= 0; k--) {
                u64 src = (k < 32) ? a0 : a1;
                u64 x = mul2(__shfl_sync(0xffffffffu, src, k & 31), pLi2[k]);
                if (k < 32) { if (lane == k) a0 = x; }
                else        { if (lane == k - 32) a1 = x; }
                u64 nx = neg2(x);
                if (lane < k) a0 = fma2(pH2[offk + lane], nx, a0);
                if (lane < 8 && 32 + lane < k) a1 = fma2(pH2[offk + 32 + lane], nx, a1);
                offk -= k;
            }
            pDU2[lane] = a0;
            if (lane < 8) pDU2[32 + lane] = a1;
        }
        __syncwarp();

        // ---- S4: ds, dlam, alpha ----
        float am0 = BIGF, am1 = BIGF;
        float ds0a[5], ds1a[5], dl0a[5], dl1a[5];
#pragma unroll
        for (int t = 0; t < 5; t++) {
            int j = lane + 32 * t;
            if (j < NINEQ) {
                u64 g;
                if (j < NU) g = pDU2[j];
                else {
                    const float4* br4 = (const float4*)(sB + (j - NU) * 44);
                    u64 acc = 0ULL;
#pragma unroll
                    for (int q = 0; q < 10; q++) {
                        float4 bv = br4[q];
                        acc = fma2(rep2(bv.x), pDU2[4 * q + 0], acc);
                        acc = fma2(rep2(bv.y), pDU2[4 * q + 1], acc);
                        acc = fma2(rep2(bv.z), pDU2[4 * q + 2], acc);
                        acc = fma2(rep2(bv.w), pDU2[4 * q + 3], acc);
                    }
                    g = acc;
                }
                float g0, g1, d0, d1, v0, v1;
                upk2(g, g0, g1);
                upk2(pD2[j], d0, d1);
                upk2(pV2[j], v0, v1);
                float ds0 = -rp0[t] - g0, ds1 = -rp1[t] - g1;
                float dl0 = v0 - rl0[t] + d0 * g0;
                float dl1 = v1 - rl1[t] + d1 * g1;
                ds0a[t] = ds0; ds1a[t] = ds1; dl0a[t] = dl0; dl1a[t] = dl1;
                float q0 = (ds0 < 0.f) ? -rs0[t] / ds0 : BIGF;
                float q1 = (dl0 < 0.f) ? -rl0[t] / dl0 : BIGF;
                am0 = fminf(am0, fminf(q0, q1));
                float q2 = (ds1 < 0.f) ? -rs1[t] / ds1 : BIGF;
                float q3 = (dl1 < 0.f) ? -rl1[t] / dl1 : BIGF;
                am1 = fminf(am1, fminf(q2, q3));
            }
        }
#pragma unroll
        for (int o = 16; o; o >>= 1) {
            am0 = fminf(am0, __shfl_xor_sync(0xffffffffu, am0, o));
            am1 = fminf(am1, __shfl_xor_sync(0xffffffffu, am1, o));
        }
        float al0 = fminf(1.0f, 0.99f * am0);
        float al1 = fminf(1.0f, 0.99f * am1);

        // ---- S5: update + mu ----
        float ls0 = 0.f, ls1 = 0.f;
#pragma unroll
        for (int t = 0; t < 5; t++) {
            int j = lane + 32 * t;
            if (j < NINEQ) {
                rs0[t] += al0 * ds0a[t];  rl0[t] += al0 * dl0a[t];  ls0 += rs0[t] * rl0[t];
                rs1[t] += al1 * ds1a[t];  rl1[t] += al1 * dl1a[t];  ls1 += rs1[t] * rl1[t];
            }
        }
#pragma unroll
        for (int o = 16; o; o >>= 1) {
            ls0 += __shfl_xor_sync(0xffffffffu, ls0, o);
            ls1 += __shfl_xor_sync(0xffffffffu, ls1, o);
        }
        mu0 = ls0 * (1.0f / 148.0f);
        mu1 = ls1 * (1.0f / 148.0f);

        u64 alp = pk2(al0, al1);
        pU2[lane] = fma2(alp, pDU2[lane], pU2[lane]);
        if (lane < 8) pU2[32 + lane] = fma2(alp, pDU2[32 + lane], pU2[32 + lane]);
        __syncwarp();
    }

    // ---- output: Q_value = 0.5 u'Qu + p'u ; u0 ----
    {
        const float4* q0 = (const float4*)(sQ + lane * 44);
        const float4* q1 = (const float4*)(sQ + (32 + lane) * 44);
        u64 qu0 = 0ULL, qu1 = 0ULL;
#pragma unroll
        for (int q = 0; q < 10; q++) {
            float4 qv0 = q0[q];
            qu0 = fma2(rep2(qv0.x), pU2[4 * q + 0], qu0);
            qu0 = fma2(rep2(qv0.y), pU2[4 * q + 1], qu0);
            qu0 = fma2(rep2(qv0.z), pU2[4 * q + 2], qu0);
            qu0 = fma2(rep2(qv0.w), pU2[4 * q + 3], qu0);
            if (lane < 8) {
                float4 qv1 = q1[q];
                qu1 = fma2(rep2(qv1.x), pU2[4 * q + 0], qu1);
                qu1 = fma2(rep2(qv1.y), pU2[4 * q + 1], qu1);
                qu1 = fma2(rep2(qv1.z), pU2[4 * q + 2], qu1);
                qu1 = fma2(rep2(qv1.w), pU2[4 * q + 3], qu1);
            }
        }
        float qa0, qa1, ua0, ua1, pa0, pa1;
        upk2(qu0, qa0, qa1);
        upk2(pU2[lane], ua0, ua1);
        upk2(pP2[lane], pa0, pa1);
        float part0 = ua0 * (0.5f * qa0 + pa0);
        float part1 = ua1 * (0.5f * qa1 + pa1);
        if (lane < 8) {
            float qb0, qb1, ub0, ub1, pb0, pb1;
            upk2(qu1, qb0, qb1);
            upk2(pU2[32 + lane], ub0, ub1);
            upk2(pP2[32 + lane], pb0, pb1);
            part0 += ub0 * (0.5f * qb0 + pb0);
            part1 += ub1 * (0.5f * qb1 + pb1);
        }
#pragma unroll
        for (int o = 16; o; o >>= 1) {
            part0 += __shfl_xor_sync(0xffffffffu, part0, o);
            part1 += __shfl_xor_sync(0xffffffffu, part1, o);
        }
        if (lane == 0) {
            float u00, u01;
            upk2(pU2[0], u00, u01);
            out[pb] = part0;
            out[pb + 1] = part1;
            out[BATCH + pb] = u00;
            out[BATCH + pb + 1] = u01;
        }
    }
}

// ================= launch =================
extern "C" void kernel_launch(void* const* d_in, const int* in_sizes, int n_in,
                              void* d_out, int out_size) {
    const float* x  = (const float*)d_in[0];
    const float* W1 = (const float*)d_in[1];
    const float* b1 = (const float*)d_in[2];
    const float* W2 = (const float*)d_in[3];
    const float* b2 = (const float*)d_in[4];
    const float* L  = (const float*)d_in[5];
    const float* LP = (const float*)d_in[6];
    const float* LR = (const float*)d_in[7];
    const float* A  = (const float*)d_in[8];
    const float* Bm = (const float*)d_in[9];
    const float* u0 = (const float*)d_in[10];
    const float* s0 = (const float*)d_in[11];

    cudaFuncSetAttribute(ipm_kernel, cudaFuncAttributeMaxDynamicSharedMemorySize, SMEM_BYTES);

    setup_kernel<<<1, 128>>>(L, LP, LR, A, Bm, u0, s0);
    mlp_kernel<<<BATCH / 4, 128>>>(x, W1, b1, W2, b2);
    ipm_kernel<<<BATCH / PPC, NTH, SMEM_BYTES>>>((float*)d_out);
}